// round 1
// baseline (speedup 1.0000x reference)
#include <cuda_runtime.h>

#define BATCH 1024
#define MDIM  1024          // OUT_FEATURES
#define NDIM  512           // IN_FEATURES
#define LAMBD 0.2f
#define TOLC  1e-4f
#define MAX_ITERS 100
#define GRID  128
#define NTHR  256

// ---------------- scratch (static device memory; no allocations) ----------------
__device__ float g_Adotb[BATCH * MDIM];
__device__ float g_v[BATCH * MDIM];
__device__ float g_u[BATCH * MDIM];
__device__ float g_vsol[BATCH * MDIM];
__device__ float g_xk[BATCH * MDIM];
__device__ int   g_flag[BATCH];
__device__ int   g_active[BATCH];
__device__ int   g_nactive;
__device__ unsigned g_count;
__device__ unsigned g_gen;

// ---------------- software grid barrier (all 128 CTAs co-resident) ----------------
__device__ __forceinline__ void gridbar() {
    __syncthreads();
    if (threadIdx.x == 0) {
        unsigned my = atomicAdd(&g_gen, 0u);
        __threadfence();
        if (atomicAdd(&g_count, 1u) == GRID - 1u) {
            atomicExch(&g_count, 0u);
            __threadfence();
            atomicAdd(&g_gen, 1u);
        } else {
            while (atomicAdd(&g_gen, 0u) == my) __nanosleep(64);
        }
        __threadfence();
    }
    __syncthreads();
}

__global__ void k_init() {
    int tid = blockIdx.x * blockDim.x + threadIdx.x;
    int nt  = gridDim.x * blockDim.x;
    for (int i = tid; i < BATCH * MDIM; i += nt) {
        g_v[i] = 0.f; g_u[i] = 0.f; g_vsol[i] = 0.f;
    }
    for (int i = tid; i < BATCH; i += nt) { g_flag[i] = 0; g_active[i] = i; }
    if (tid == 0) { g_nactive = BATCH; g_count = 0u; g_gen = 0u; }
}

__device__ __forceinline__ float sshrink(float x) {
    return x > LAMBD ? x - LAMBD : (x < -LAMBD ? x + LAMBD : 0.f);
}

// one k-step of the 64x128 tile: 4x8 fragment per thread
__device__ __forceinline__ void mma_step(float acc[4][8], const float* Asrow,
                                         const float* Bsrow, int ty, int tx) {
    float4 a4 = *(const float4*)(Asrow + ty * 4);
    float4 b0 = *(const float4*)(Bsrow + tx * 8);
    float4 b1 = *(const float4*)(Bsrow + tx * 8 + 4);
    float av[4] = {a4.x, a4.y, a4.z, a4.w};
    float bv[8] = {b0.x, b0.y, b0.z, b0.w, b1.x, b1.y, b1.z, b1.w};
#pragma unroll
    for (int r = 0; r < 4; ++r)
#pragma unroll
        for (int c = 0; c < 8; ++c) acc[r][c] += av[r] * bv[c];
}

// ---------------- persistent ADMM kernel ----------------
__global__ __launch_bounds__(NTHR, 1) void k_admm(const float* __restrict__ x,
                                                  const float* __restrict__ w,
                                                  const float* __restrict__ Minv) {
    __shared__ __align__(16) float As[2][16][68];
    __shared__ __align__(16) float Bs[2][16][128];
    __shared__ int   s_row[64];
    __shared__ float s_red[16];
    __shared__ int   s_conv;
    __shared__ int   s_cnt;

    const int tid = threadIdx.x;
    const int tx = tid & 15, ty = tid >> 4;
    const int ai = tid >> 2, akq = tid & 3;   // A-tile loads: row ai, k-quad akq
    const int bk = tid >> 4, bj = tid & 15;   // B-tile loads (NN gemms)

    // ======== Phase A: Adotb = x @ w^T  (1024x1024x512, NT) ========
    {
        int tm = blockIdx.x >> 3, tn = blockIdx.x & 7;
        float acc[4][8];
#pragma unroll
        for (int r = 0; r < 4; ++r)
#pragma unroll
            for (int c = 0; c < 8; ++c) acc[r][c] = 0.f;

        const float* pa = x + (tm * 64 + ai) * NDIM + akq * 4;
        int bm = tid >> 1, bkh = tid & 1;
        const float* pb = w + (tn * 128 + bm) * NDIM + bkh * 8;

        for (int kc = 0; kc < NDIM / 16; ++kc) {
            float4 a = *(const float4*)(pa + kc * 16);
            As[0][akq * 4 + 0][ai] = a.x;
            As[0][akq * 4 + 1][ai] = a.y;
            As[0][akq * 4 + 2][ai] = a.z;
            As[0][akq * 4 + 3][ai] = a.w;
            float4 b0v = *(const float4*)(pb + kc * 16);
            float4 b1v = *(const float4*)(pb + kc * 16 + 4);
            Bs[0][bkh * 8 + 0][bm] = b0v.x;
            Bs[0][bkh * 8 + 1][bm] = b0v.y;
            Bs[0][bkh * 8 + 2][bm] = b0v.z;
            Bs[0][bkh * 8 + 3][bm] = b0v.w;
            Bs[0][bkh * 8 + 4][bm] = b1v.x;
            Bs[0][bkh * 8 + 5][bm] = b1v.y;
            Bs[0][bkh * 8 + 6][bm] = b1v.z;
            Bs[0][bkh * 8 + 7][bm] = b1v.w;
            __syncthreads();
#pragma unroll
            for (int kk = 0; kk < 16; ++kk)
                mma_step(acc, &As[0][kk][0], &Bs[0][kk][0], ty, tx);
            __syncthreads();
        }
#pragma unroll
        for (int r = 0; r < 4; ++r) {
            float* po = g_Adotb + (tm * 64 + ty * 4 + r) * MDIM + tn * 128 + tx * 8;
            *(float4*)po       = make_float4(acc[r][0], acc[r][1], acc[r][2], acc[r][3]);
            *(float4*)(po + 4) = make_float4(acc[r][4], acc[r][5], acc[r][6], acc[r][7]);
        }
    }
    gridbar();

    // ======== ADMM loop ========
    for (int it = 0; it < MAX_ITERS; ++it) {
        int nact = g_nactive;     // consistent: written by CTA0 before last barrier
        if (nact == 0) break;
        int ntm = (nact + 63) >> 6;

        // ---- xk[active] = (Adotb + v - u)[active] @ Minv  (NN, K=1024) ----
        for (int t = blockIdx.x; t < ntm * 8; t += GRID) {
            int tm = t >> 3, tn = t & 7;
            if (tid < 64) {
                int rr = tm * 64 + tid;
                s_row[tid] = g_active[rr < nact ? rr : nact - 1];
            }
            __syncthreads();
            int arow = s_row[ai];
            const float* pa = g_Adotb + arow * MDIM + akq * 4;
            const float* pv = g_v + arow * MDIM + akq * 4;
            const float* pu = g_u + arow * MDIM + akq * 4;
            const float* pb = Minv + bk * MDIM + tn * 128 + bj * 8;

            float acc[4][8];
#pragma unroll
            for (int r = 0; r < 4; ++r)
#pragma unroll
                for (int c = 0; c < 8; ++c) acc[r][c] = 0.f;

            // prologue: chunk 0 -> buf 0
            {
                float4 a  = *(const float4*)(pa);
                float4 vv = *(const float4*)(pv);
                float4 uu = *(const float4*)(pu);
                As[0][akq * 4 + 0][ai] = a.x + vv.x - uu.x;
                As[0][akq * 4 + 1][ai] = a.y + vv.y - uu.y;
                As[0][akq * 4 + 2][ai] = a.z + vv.z - uu.z;
                As[0][akq * 4 + 3][ai] = a.w + vv.w - uu.w;
                float4 b0v = *(const float4*)(pb);
                float4 b1v = *(const float4*)(pb + 4);
                *(float4*)&Bs[0][bk][bj * 8]     = b0v;
                *(float4*)&Bs[0][bk][bj * 8 + 4] = b1v;
            }
            __syncthreads();
            for (int kc = 0; kc < MDIM / 16; ++kc) {
                int cur = kc & 1;
                if (kc + 1 < MDIM / 16) {
                    int nb = cur ^ 1;
                    float4 a  = *(const float4*)(pa + (kc + 1) * 16);
                    float4 vv = *(const float4*)(pv + (kc + 1) * 16);
                    float4 uu = *(const float4*)(pu + (kc + 1) * 16);
                    As[nb][akq * 4 + 0][ai] = a.x + vv.x - uu.x;
                    As[nb][akq * 4 + 1][ai] = a.y + vv.y - uu.y;
                    As[nb][akq * 4 + 2][ai] = a.z + vv.z - uu.z;
                    As[nb][akq * 4 + 3][ai] = a.w + vv.w - uu.w;
                    float4 b0v = *(const float4*)(pb + (kc + 1) * 16 * MDIM);
                    float4 b1v = *(const float4*)(pb + (kc + 1) * 16 * MDIM + 4);
                    *(float4*)&Bs[nb][bk][bj * 8]     = b0v;
                    *(float4*)&Bs[nb][bk][bj * 8 + 4] = b1v;
                }
#pragma unroll
                for (int kk = 0; kk < 16; ++kk)
                    mma_step(acc, &As[cur][kk][0], &Bs[cur][kk][0], ty, tx);
                __syncthreads();
            }
#pragma unroll
            for (int r = 0; r < 4; ++r) {
                int lr = tm * 64 + ty * 4 + r;
                if (lr < nact) {
                    int row = s_row[ty * 4 + r];
                    float* po = g_xk + row * MDIM + tn * 128 + tx * 8;
                    *(float4*)po       = make_float4(acc[r][0], acc[r][1], acc[r][2], acc[r][3]);
                    *(float4*)(po + 4) = make_float4(acc[r][4], acc[r][5], acc[r][6], acc[r][7]);
                }
            }
            __syncthreads();
        }
        gridbar();

        // ---- elementwise update + convergence (one row per CTA pass) ----
        for (int rr = blockIdx.x; rr < nact; rr += GRID) {
            int row = g_active[rr];
            float4 xk4 = *((const float4*)(g_xk + row * MDIM) + tid);
            float4 v4  = *((const float4*)(g_v  + row * MDIM) + tid);
            float4 u4  = *((const float4*)(g_u  + row * MDIM) + tid);
            float4 vn, un;
            float xi, d;
            float dx2 = 0.f, x2 = 0.f;
            xi = xk4.x + u4.x; vn.x = sshrink(xi); un.x = xi - vn.x;
            d = vn.x - v4.x; dx2 += d * d; x2 += vn.x * vn.x;
            xi = xk4.y + u4.y; vn.y = sshrink(xi); un.y = xi - vn.y;
            d = vn.y - v4.y; dx2 += d * d; x2 += vn.y * vn.y;
            xi = xk4.z + u4.z; vn.z = sshrink(xi); un.z = xi - vn.z;
            d = vn.z - v4.z; dx2 += d * d; x2 += vn.z * vn.z;
            xi = xk4.w + u4.w; vn.w = sshrink(xi); un.w = xi - vn.w;
            d = vn.w - v4.w; dx2 += d * d; x2 += vn.w * vn.w;

#pragma unroll
            for (int o = 16; o; o >>= 1) {
                dx2 += __shfl_xor_sync(0xffffffffu, dx2, o);
                x2  += __shfl_xor_sync(0xffffffffu, x2, o);
            }
            if ((tid & 31) == 0) { s_red[tid >> 5] = dx2; s_red[8 + (tid >> 5)] = x2; }
            __syncthreads();
            if (tid == 0) {
                float dd = 0.f, xx = 0.f;
#pragma unroll
                for (int i = 0; i < 8; ++i) { dd += s_red[i]; xx += s_red[8 + i]; }
                // NaN (0/0) compares false, matching the reference
                s_conv = (sqrtf(dd) / sqrtf(xx) < TOLC) ? 1 : 0;
            }
            __syncthreads();
            if (s_conv) {
                *((float4*)(g_vsol + row * MDIM) + tid) = vn;
                if (tid == 0) g_flag[row] = 1;
            } else {
                *((float4*)(g_v + row * MDIM) + tid) = vn;
                *((float4*)(g_u + row * MDIM) + tid) = un;
            }
            __syncthreads();
        }
        gridbar();

        // ---- compaction of active rows (CTA 0) ----
        if (blockIdx.x == 0) {
            if (tid == 0) s_cnt = 0;
            __syncthreads();
            for (int i = tid; i < BATCH; i += NTHR) {
                if (!g_flag[i]) {
                    int p = atomicAdd(&s_cnt, 1);
                    g_active[p] = i;
                }
            }
            __syncthreads();
            if (tid == 0) g_nactive = s_cnt;
        }
        gridbar();
    }
}

// ---------------- decode: enc = vsol ; dec = vsol @ w  (1024x512x1024, NN) ----------------
__global__ __launch_bounds__(NTHR, 1) void k_decode(const float* __restrict__ w,
                                                    float* __restrict__ enc,
                                                    float* __restrict__ dec) {
    __shared__ __align__(16) float As[2][16][68];
    __shared__ __align__(16) float Bs[2][16][128];
    const int tid = threadIdx.x;
    const int tx = tid & 15, ty = tid >> 4;
    const int ai = tid >> 2, akq = tid & 3;
    const int bk = tid >> 4, bj = tid & 15;

    if (enc) {
        const float4* src = (const float4*)g_vsol;
        float4* dst = (float4*)enc;
        int gt = blockIdx.x * NTHR + tid;
        int nt = gridDim.x * NTHR;
        for (int i = gt; i < BATCH * MDIM / 4; i += nt) dst[i] = src[i];
    }
    if (!dec) return;

    int tm = blockIdx.x >> 2, tn = blockIdx.x & 3;
    const float* pa = g_vsol + (tm * 64 + ai) * MDIM + akq * 4;
    const float* pb = w + bk * NDIM + tn * 128 + bj * 8;

    float acc[4][8];
#pragma unroll
    for (int r = 0; r < 4; ++r)
#pragma unroll
        for (int c = 0; c < 8; ++c) acc[r][c] = 0.f;

    {
        float4 a = *(const float4*)(pa);
        As[0][akq * 4 + 0][ai] = a.x;
        As[0][akq * 4 + 1][ai] = a.y;
        As[0][akq * 4 + 2][ai] = a.z;
        As[0][akq * 4 + 3][ai] = a.w;
        float4 b0v = *(const float4*)(pb);
        float4 b1v = *(const float4*)(pb + 4);
        *(float4*)&Bs[0][bk][bj * 8]     = b0v;
        *(float4*)&Bs[0][bk][bj * 8 + 4] = b1v;
    }
    __syncthreads();
    for (int kc = 0; kc < MDIM / 16; ++kc) {
        int cur = kc & 1;
        if (kc + 1 < MDIM / 16) {
            int nb = cur ^ 1;
            float4 a = *(const float4*)(pa + (kc + 1) * 16);
            As[nb][akq * 4 + 0][ai] = a.x;
            As[nb][akq * 4 + 1][ai] = a.y;
            As[nb][akq * 4 + 2][ai] = a.z;
            As[nb][akq * 4 + 3][ai] = a.w;
            float4 b0v = *(const float4*)(pb + (kc + 1) * 16 * NDIM);
            float4 b1v = *(const float4*)(pb + (kc + 1) * 16 * NDIM + 4);
            *(float4*)&Bs[nb][bk][bj * 8]     = b0v;
            *(float4*)&Bs[nb][bk][bj * 8 + 4] = b1v;
        }
#pragma unroll
        for (int kk = 0; kk < 16; ++kk)
            mma_step(acc, &As[cur][kk][0], &Bs[cur][kk][0], ty, tx);
        __syncthreads();
    }
#pragma unroll
    for (int r = 0; r < 4; ++r) {
        float* po = dec + (tm * 64 + ty * 4 + r) * NDIM + tn * 128 + tx * 8;
        *(float4*)po       = make_float4(acc[r][0], acc[r][1], acc[r][2], acc[r][3]);
        *(float4*)(po + 4) = make_float4(acc[r][4], acc[r][5], acc[r][6], acc[r][7]);
    }
}

extern "C" void kernel_launch(void* const* d_in, const int* in_sizes, int n_in,
                              void* d_out, int out_size) {
    // inputs (setup order): x [1024*512], weight [1024*512], M_inv [1024*1024]
    const float* x = nullptr;
    const float* w = nullptr;
    const float* Minv = nullptr;
    int small[2] = {0, 1};
    int si = 0;
    for (int i = 0; i < n_in; ++i) {
        if (in_sizes[i] == MDIM * MDIM && !Minv) {
            Minv = (const float*)d_in[i];
        } else if (si < 2) {
            small[si++] = i;
        }
    }
    x = (const float*)d_in[small[0]];
    w = (const float*)d_in[small[1]];

    float* out = (float*)d_out;
    float* enc = nullptr;
    float* dec = nullptr;
    if (out_size >= BATCH * MDIM + BATCH * NDIM) {
        enc = out;
        dec = out + (size_t)BATCH * MDIM;
    } else if (out_size == BATCH * MDIM) {
        enc = out;
    } else if (out_size == BATCH * NDIM) {
        dec = out;
    } else {
        enc = out;  // fallback
    }

    k_init<<<128, 256>>>();
    k_admm<<<GRID, NTHR>>>(x, w, Minv);
    k_decode<<<64, NTHR>>>(w, enc, dec);
}

// round 2
// speedup vs baseline: 1.0704x; 1.0704x over previous
#include <cuda_runtime.h>

#define BATCH 1024
#define MDIM  1024          // OUT_FEATURES
#define NDIM  512           // IN_FEATURES
#define LAMBD 0.2f
#define TOLC  1e-4f
#define MAX_ITERS 100
#define GRID  128
#define NTHR  256

// ---------------- scratch (static device memory; no allocations) ----------------
__device__ float g_Adotb[BATCH * MDIM];
__device__ float g_v[BATCH * MDIM];
__device__ float g_u[BATCH * MDIM];
__device__ float g_vsol[BATCH * MDIM];
__device__ float g_xk[BATCH * MDIM];
__device__ int   g_flag[BATCH];
__device__ int   g_active[BATCH];
__device__ int   g_nactive;
__device__ unsigned g_count;
__device__ unsigned g_gen;

// ---------------- software grid barrier (all 128 CTAs co-resident) ----------------
__device__ __forceinline__ void gridbar() {
    __syncthreads();
    if (threadIdx.x == 0) {
        unsigned my = atomicAdd(&g_gen, 0u);
        __threadfence();
        if (atomicAdd(&g_count, 1u) == GRID - 1u) {
            atomicExch(&g_count, 0u);
            __threadfence();
            atomicAdd(&g_gen, 1u);
        } else {
            while (atomicAdd(&g_gen, 0u) == my) __nanosleep(64);
        }
        __threadfence();
    }
    __syncthreads();
}

__global__ void k_init() {
    int tid = blockIdx.x * blockDim.x + threadIdx.x;
    int nt  = gridDim.x * blockDim.x;
    for (int i = tid; i < BATCH * MDIM; i += nt) {
        g_v[i] = 0.f; g_u[i] = 0.f; g_vsol[i] = 0.f;
    }
    for (int i = tid; i < BATCH; i += nt) { g_flag[i] = 0; g_active[i] = i; }
    if (tid == 0) { g_nactive = BATCH; g_count = 0u; g_gen = 0u; }
}

__device__ __forceinline__ float sshrink(float x) {
    return x > LAMBD ? x - LAMBD : (x < -LAMBD ? x + LAMBD : 0.f);
}

// one k-step of the 64x128 tile: 4x8 fragment per thread
__device__ __forceinline__ void mma_step(float acc[4][8], const float* Asrow,
                                         const float* Bsrow, int ty, int tx) {
    float4 a4 = *(const float4*)(Asrow + ty * 4);
    float4 b0 = *(const float4*)(Bsrow + tx * 8);
    float4 b1 = *(const float4*)(Bsrow + tx * 8 + 4);
    float av[4] = {a4.x, a4.y, a4.z, a4.w};
    float bv[8] = {b0.x, b0.y, b0.z, b0.w, b1.x, b1.y, b1.z, b1.w};
#pragma unroll
    for (int r = 0; r < 4; ++r)
#pragma unroll
        for (int c = 0; c < 8; ++c) acc[r][c] += av[r] * bv[c];
}

// ---------------- persistent ADMM kernel ----------------
__global__ __launch_bounds__(NTHR, 1) void k_admm(const float* __restrict__ x,
                                                  const float* __restrict__ w,
                                                  const float* __restrict__ Minv) {
    __shared__ __align__(16) float As[2][16][68];
    __shared__ __align__(16) float Bs[2][16][128];
    __shared__ int   s_row[64];
    __shared__ float s_red[16];
    __shared__ int   s_conv;
    __shared__ int   s_cnt;

    const int tid = threadIdx.x;
    const int tx = tid & 15, ty = tid >> 4;
    const int ai = tid >> 2, akq = tid & 3;   // A-tile loads: row ai, k-quad akq
    const int bk = tid >> 4, bj = tid & 15;   // B-tile loads (NN gemms)

    // ======== Phase A: Adotb = x @ w^T  (1024x1024x512, NT) ========
    {
        int tm = blockIdx.x >> 3, tn = blockIdx.x & 7;
        float acc[4][8];
#pragma unroll
        for (int r = 0; r < 4; ++r)
#pragma unroll
            for (int c = 0; c < 8; ++c) acc[r][c] = 0.f;

        const float* pa = x + (tm * 64 + ai) * NDIM + akq * 4;
        int bm = tid >> 1, bkh = tid & 1;
        const float* pb = w + (tn * 128 + bm) * NDIM + bkh * 8;

        for (int kc = 0; kc < NDIM / 16; ++kc) {
            float4 a = *(const float4*)(pa + kc * 16);
            As[0][akq * 4 + 0][ai] = a.x;
            As[0][akq * 4 + 1][ai] = a.y;
            As[0][akq * 4 + 2][ai] = a.z;
            As[0][akq * 4 + 3][ai] = a.w;
            float4 b0v = *(const float4*)(pb + kc * 16);
            float4 b1v = *(const float4*)(pb + kc * 16 + 4);
            Bs[0][bkh * 8 + 0][bm] = b0v.x;
            Bs[0][bkh * 8 + 1][bm] = b0v.y;
            Bs[0][bkh * 8 + 2][bm] = b0v.z;
            Bs[0][bkh * 8 + 3][bm] = b0v.w;
            Bs[0][bkh * 8 + 4][bm] = b1v.x;
            Bs[0][bkh * 8 + 5][bm] = b1v.y;
            Bs[0][bkh * 8 + 6][bm] = b1v.z;
            Bs[0][bkh * 8 + 7][bm] = b1v.w;
            __syncthreads();
#pragma unroll
            for (int kk = 0; kk < 16; ++kk)
                mma_step(acc, &As[0][kk][0], &Bs[0][kk][0], ty, tx);
            __syncthreads();
        }
#pragma unroll
        for (int r = 0; r < 4; ++r) {
            float* po = g_Adotb + (tm * 64 + ty * 4 + r) * MDIM + tn * 128 + tx * 8;
            *(float4*)po       = make_float4(acc[r][0], acc[r][1], acc[r][2], acc[r][3]);
            *(float4*)(po + 4) = make_float4(acc[r][4], acc[r][5], acc[r][6], acc[r][7]);
        }
    }
    gridbar();

    // ======== ADMM loop ========
    for (int it = 0; it < MAX_ITERS; ++it) {
        int nact = g_nactive;     // consistent: written by CTA0 before last barrier
        if (nact == 0) break;
        int ntm = (nact + 63) >> 6;

        // ---- xk[active] = (Adotb + v - u)[active] @ Minv  (NN, K=1024) ----
        for (int t = blockIdx.x; t < ntm * 8; t += GRID) {
            int tm = t >> 3, tn = t & 7;
            if (tid < 64) {
                int rr = tm * 64 + tid;
                s_row[tid] = g_active[rr < nact ? rr : nact - 1];
            }
            __syncthreads();
            int arow = s_row[ai];
            const float* pa = g_Adotb + arow * MDIM + akq * 4;
            const float* pv = g_v + arow * MDIM + akq * 4;
            const float* pu = g_u + arow * MDIM + akq * 4;
            const float* pb = Minv + bk * MDIM + tn * 128 + bj * 8;

            float acc[4][8];
#pragma unroll
            for (int r = 0; r < 4; ++r)
#pragma unroll
                for (int c = 0; c < 8; ++c) acc[r][c] = 0.f;

            // prologue: chunk 0 -> buf 0
            {
                float4 a  = *(const float4*)(pa);
                float4 vv = *(const float4*)(pv);
                float4 uu = *(const float4*)(pu);
                As[0][akq * 4 + 0][ai] = a.x + vv.x - uu.x;
                As[0][akq * 4 + 1][ai] = a.y + vv.y - uu.y;
                As[0][akq * 4 + 2][ai] = a.z + vv.z - uu.z;
                As[0][akq * 4 + 3][ai] = a.w + vv.w - uu.w;
                float4 b0v = *(const float4*)(pb);
                float4 b1v = *(const float4*)(pb + 4);
                *(float4*)&Bs[0][bk][bj * 8]     = b0v;
                *(float4*)&Bs[0][bk][bj * 8 + 4] = b1v;
            }
            __syncthreads();
            for (int kc = 0; kc < MDIM / 16; ++kc) {
                int cur = kc & 1;
                if (kc + 1 < MDIM / 16) {
                    int nb = cur ^ 1;
                    float4 a  = *(const float4*)(pa + (kc + 1) * 16);
                    float4 vv = *(const float4*)(pv + (kc + 1) * 16);
                    float4 uu = *(const float4*)(pu + (kc + 1) * 16);
                    As[nb][akq * 4 + 0][ai] = a.x + vv.x - uu.x;
                    As[nb][akq * 4 + 1][ai] = a.y + vv.y - uu.y;
                    As[nb][akq * 4 + 2][ai] = a.z + vv.z - uu.z;
                    As[nb][akq * 4 + 3][ai] = a.w + vv.w - uu.w;
                    float4 b0v = *(const float4*)(pb + (kc + 1) * 16 * MDIM);
                    float4 b1v = *(const float4*)(pb + (kc + 1) * 16 * MDIM + 4);
                    *(float4*)&Bs[nb][bk][bj * 8]     = b0v;
                    *(float4*)&Bs[nb][bk][bj * 8 + 4] = b1v;
                }
#pragma unroll
                for (int kk = 0; kk < 16; ++kk)
                    mma_step(acc, &As[cur][kk][0], &Bs[cur][kk][0], ty, tx);
                __syncthreads();
            }
#pragma unroll
            for (int r = 0; r < 4; ++r) {
                int lr = tm * 64 + ty * 4 + r;
                if (lr < nact) {
                    int row = s_row[ty * 4 + r];
                    float* po = g_xk + row * MDIM + tn * 128 + tx * 8;
                    *(float4*)po       = make_float4(acc[r][0], acc[r][1], acc[r][2], acc[r][3]);
                    *(float4*)(po + 4) = make_float4(acc[r][4], acc[r][5], acc[r][6], acc[r][7]);
                }
            }
            __syncthreads();
        }
        gridbar();

        // ---- elementwise update + convergence (one row per CTA pass) ----
        for (int rr = blockIdx.x; rr < nact; rr += GRID) {
            int row = g_active[rr];
            float4 xk4 = *((const float4*)(g_xk + row * MDIM) + tid);
            float4 v4  = *((const float4*)(g_v  + row * MDIM) + tid);
            float4 u4  = *((const float4*)(g_u  + row * MDIM) + tid);
            float4 vn, un;
            float xi, d;
            float dx2 = 0.f, x2 = 0.f;
            xi = xk4.x + u4.x; vn.x = sshrink(xi); un.x = xi - vn.x;
            d = vn.x - v4.x; dx2 += d * d; x2 += vn.x * vn.x;
            xi = xk4.y + u4.y; vn.y = sshrink(xi); un.y = xi - vn.y;
            d = vn.y - v4.y; dx2 += d * d; x2 += vn.y * vn.y;
            xi = xk4.z + u4.z; vn.z = sshrink(xi); un.z = xi - vn.z;
            d = vn.z - v4.z; dx2 += d * d; x2 += vn.z * vn.z;
            xi = xk4.w + u4.w; vn.w = sshrink(xi); un.w = xi - vn.w;
            d = vn.w - v4.w; dx2 += d * d; x2 += vn.w * vn.w;

#pragma unroll
            for (int o = 16; o; o >>= 1) {
                dx2 += __shfl_xor_sync(0xffffffffu, dx2, o);
                x2  += __shfl_xor_sync(0xffffffffu, x2, o);
            }
            if ((tid & 31) == 0) { s_red[tid >> 5] = dx2; s_red[8 + (tid >> 5)] = x2; }
            __syncthreads();
            if (tid == 0) {
                float dd = 0.f, xx = 0.f;
#pragma unroll
                for (int i = 0; i < 8; ++i) { dd += s_red[i]; xx += s_red[8 + i]; }
                // NaN (0/0) compares false, matching the reference
                s_conv = (sqrtf(dd) / sqrtf(xx) < TOLC) ? 1 : 0;
            }
            __syncthreads();
            if (s_conv) {
                *((float4*)(g_vsol + row * MDIM) + tid) = vn;
                if (tid == 0) g_flag[row] = 1;
            } else {
                *((float4*)(g_v + row * MDIM) + tid) = vn;
                *((float4*)(g_u + row * MDIM) + tid) = un;
            }
            __syncthreads();
        }
        gridbar();

        // ---- compaction of active rows (CTA 0) ----
        if (blockIdx.x == 0) {
            if (tid == 0) s_cnt = 0;
            __syncthreads();
            for (int i = tid; i < BATCH; i += NTHR) {
                if (!g_flag[i]) {
                    int p = atomicAdd(&s_cnt, 1);
                    g_active[p] = i;
                }
            }
            __syncthreads();
            if (tid == 0) g_nactive = s_cnt;
        }
        gridbar();
    }
}

// ---------------- decode: enc = vsol ; dec = vsol @ w  (1024x512x1024, NN) ----------------
__global__ __launch_bounds__(NTHR, 1) void k_decode(const float* __restrict__ w,
                                                    float* __restrict__ enc,
                                                    float* __restrict__ dec) {
    __shared__ __align__(16) float As[2][16][68];
    __shared__ __align__(16) float Bs[2][16][128];
    const int tid = threadIdx.x;
    const int tx = tid & 15, ty = tid >> 4;
    const int ai = tid >> 2, akq = tid & 3;
    const int bk = tid >> 4, bj = tid & 15;

    if (enc) {
        const float4* src = (const float4*)g_vsol;
        float4* dst = (float4*)enc;
        int gt = blockIdx.x * NTHR + tid;
        int nt = gridDim.x * NTHR;
        for (int i = gt; i < BATCH * MDIM / 4; i += nt) dst[i] = src[i];
    }
    if (!dec) return;

    int tm = blockIdx.x >> 2, tn = blockIdx.x & 3;
    const float* pa = g_vsol + (tm * 64 + ai) * MDIM + akq * 4;
    const float* pb = w + bk * NDIM + tn * 128 + bj * 8;

    float acc[4][8];
#pragma unroll
    for (int r = 0; r < 4; ++r)
#pragma unroll
        for (int c = 0; c < 8; ++c) acc[r][c] = 0.f;

    {
        float4 a = *(const float4*)(pa);
        As[0][akq * 4 + 0][ai] = a.x;
        As[0][akq * 4 + 1][ai] = a.y;
        As[0][akq * 4 + 2][ai] = a.z;
        As[0][akq * 4 + 3][ai] = a.w;
        float4 b0v = *(const float4*)(pb);
        float4 b1v = *(const float4*)(pb + 4);
        *(float4*)&Bs[0][bk][bj * 8]     = b0v;
        *(float4*)&Bs[0][bk][bj * 8 + 4] = b1v;
    }
    __syncthreads();
    for (int kc = 0; kc < MDIM / 16; ++kc) {
        int cur = kc & 1;
        if (kc + 1 < MDIM / 16) {
            int nb = cur ^ 1;
            float4 a = *(const float4*)(pa + (kc + 1) * 16);
            As[nb][akq * 4 + 0][ai] = a.x;
            As[nb][akq * 4 + 1][ai] = a.y;
            As[nb][akq * 4 + 2][ai] = a.z;
            As[nb][akq * 4 + 3][ai] = a.w;
            float4 b0v = *(const float4*)(pb + (kc + 1) * 16 * NDIM);
            float4 b1v = *(const float4*)(pb + (kc + 1) * 16 * NDIM + 4);
            *(float4*)&Bs[nb][bk][bj * 8]     = b0v;
            *(float4*)&Bs[nb][bk][bj * 8 + 4] = b1v;
        }
#pragma unroll
        for (int kk = 0; kk < 16; ++kk)
            mma_step(acc, &As[cur][kk][0], &Bs[cur][kk][0], ty, tx);
        __syncthreads();
    }
#pragma unroll
    for (int r = 0; r < 4; ++r) {
        float* po = dec + (tm * 64 + ty * 4 + r) * NDIM + tn * 128 + tx * 8;
        *(float4*)po       = make_float4(acc[r][0], acc[r][1], acc[r][2], acc[r][3]);
        *(float4*)(po + 4) = make_float4(acc[r][4], acc[r][5], acc[r][6], acc[r][7]);
    }
}

extern "C" void kernel_launch(void* const* d_in, const int* in_sizes, int n_in,
                              void* d_out, int out_size) {
    // inputs (setup order): x [1024*512], weight [1024*512], M_inv [1024*1024]
    const float* x = nullptr;
    const float* w = nullptr;
    const float* Minv = nullptr;
    int small[2] = {0, 1};
    int si = 0;
    for (int i = 0; i < n_in; ++i) {
        if (in_sizes[i] == MDIM * MDIM && !Minv) {
            Minv = (const float*)d_in[i];
        } else if (si < 2) {
            small[si++] = i;
        }
    }
    x = (const float*)d_in[small[0]];
    w = (const float*)d_in[small[1]];

    float* out = (float*)d_out;
    float* enc = nullptr;
    float* dec = nullptr;
    if (out_size >= BATCH * MDIM + BATCH * NDIM) {
        enc = out;
        dec = out + (size_t)BATCH * MDIM;
    } else if (out_size == BATCH * MDIM) {
        enc = out;
    } else if (out_size == BATCH * NDIM) {
        dec = out;
    } else {
        enc = out;  // fallback
    }

    k_init<<<128, 256>>>();
    k_admm<<<GRID, NTHR>>>(x, w, Minv);
    k_decode<<<64, NTHR>>>(w, enc, dec);
}

// round 4
// speedup vs baseline: 1.9347x; 1.8074x over previous
#include <cuda_runtime.h>
#include <cuda_bf16.h>
#include <cstdint>

#define BATCH 1024
#define MDIM  1024
#define NDIM  512
#define LAMBD 0.2f
#define TOLC  1e-4f
#define MAX_ITERS 100
#define GRID  128
#define NTHR  256
#define NSTAGE 96

// dynamic smem layout (bytes)
#define SM_RED   64
#define SM_CONV  192
#define SM_SCAN  256        // 257 ints
#define SM_ACT   2560       // 1024 ints
#define SM_A0    8192       // A stage buffers 2 x 8KB
#define SM_B0    24576      // B stage buffers 2 x 8KB
#define SMEM_TOTAL 40960

__device__ __align__(16) float g_Adotb[BATCH * MDIM];
__device__ __align__(16) float g_v[BATCH * MDIM];
__device__ __align__(16) float g_u[BATCH * MDIM];
__device__ __align__(16) float g_vsol[BATCH * MDIM];
__device__ __align__(16) float g_xkA[BATCH * MDIM];
__device__ __align__(16) float g_xkB[BATCH * MDIM];
__device__ __align__(16) __nv_bfloat16 g_Eh[BATCH * MDIM];
__device__ __align__(16) __nv_bfloat16 g_Em[BATCH * MDIM];
__device__ __align__(16) __nv_bfloat16 g_El[BATCH * MDIM];
__device__ __align__(16) __nv_bfloat16 g_Bh[MDIM * MDIM];   // B[n][k] = Minv[k][n]
__device__ __align__(16) __nv_bfloat16 g_Bm[MDIM * MDIM];
__device__ __align__(16) __nv_bfloat16 g_Bl[MDIM * MDIM];
__device__ int g_flag[BATCH];
__device__ unsigned g_count, g_gen;

// ---------- helpers ----------
__device__ __forceinline__ uint32_t smem_u32(const void* p) {
    uint32_t a;
    asm("{ .reg .u64 t; cvta.to.shared.u64 t, %1; cvt.u32.u64 %0, t; }" : "=r"(a) : "l"(p));
    return a;
}
// SW64 swizzle for 64B-stride rows (conflict-free ldmatrix)
__device__ __forceinline__ uint32_t swz(uint32_t o) { return o ^ ((o >> 3) & 0x30); }

__device__ __forceinline__ void cp16(uint32_t d, const void* s) {
    asm volatile("cp.async.cg.shared.global [%0], [%1], 16;" :: "r"(d), "l"(s));
}
__device__ __forceinline__ void cp_commit() { asm volatile("cp.async.commit_group;" ::: "memory"); }
template <int N> __device__ __forceinline__ void cp_wait() {
    asm volatile("cp.async.wait_group %0;" :: "n"(N) : "memory");
}
__device__ __forceinline__ void ldsm_x4(uint32_t& r0, uint32_t& r1, uint32_t& r2,
                                        uint32_t& r3, uint32_t a) {
    asm volatile("ldmatrix.sync.aligned.m8n8.x4.shared.b16 {%0,%1,%2,%3}, [%4];"
                 : "=r"(r0), "=r"(r1), "=r"(r2), "=r"(r3) : "r"(a));
}
__device__ __forceinline__ void ldsm_x2t(uint32_t& r0, uint32_t& r1, uint32_t a) {
    asm volatile("ldmatrix.sync.aligned.m8n8.x2.trans.shared.b16 {%0,%1}, [%2];"
                 : "=r"(r0), "=r"(r1) : "r"(a));
}
__device__ __forceinline__ void mma16816(float d[4], const uint32_t a[4], const uint32_t b[2]) {
    asm volatile(
        "mma.sync.aligned.m16n8k16.row.col.f32.bf16.bf16.f32 "
        "{%0,%1,%2,%3}, {%4,%5,%6,%7}, {%8,%9}, {%0,%1,%2,%3};"
        : "+f"(d[0]), "+f"(d[1]), "+f"(d[2]), "+f"(d[3])
        : "r"(a[0]), "r"(a[1]), "r"(a[2]), "r"(a[3]), "r"(b[0]), "r"(b[1]));
}

__device__ __forceinline__ void gridbar() {
    __syncthreads();
    if (threadIdx.x == 0) {
        unsigned my = atomicAdd(&g_gen, 0u);
        __threadfence();
        if (atomicAdd(&g_count, 1u) == GRID - 1u) {
            atomicExch(&g_count, 0u);
            __threadfence();
            atomicAdd(&g_gen, 1u);
        } else {
            while (atomicAdd(&g_gen, 0u) == my) __nanosleep(64);
        }
        __threadfence();
    }
    __syncthreads();
}

__device__ __forceinline__ float sshrink(float x) {
    return x > LAMBD ? x - LAMBD : (x < -LAMBD ? x + LAMBD : 0.f);
}
__device__ __forceinline__ void split3(float a, __nv_bfloat16& h, __nv_bfloat16& m,
                                       __nv_bfloat16& l) {
    h = __float2bfloat16(a);
    float r = a - __bfloat162float(h);
    m = __float2bfloat16(r);
    l = __float2bfloat16(r - __bfloat162float(m));
}

__global__ void k_init() {
    int tid = blockIdx.x * blockDim.x + threadIdx.x, nt = gridDim.x * blockDim.x;
    float4 z = make_float4(0.f, 0.f, 0.f, 0.f);
    for (int i = tid; i < BATCH * MDIM / 4; i += nt) {
        ((float4*)g_v)[i] = z; ((float4*)g_u)[i] = z; ((float4*)g_vsol)[i] = z;
    }
    for (int i = tid; i < BATCH; i += nt) g_flag[i] = 0;
    if (tid == 0) { g_count = 0u; g_gen = 0u; }
}

// transpose + 3-way bf16 split of Minv
__global__ void k_prep(const float* __restrict__ Minv) {
    __shared__ float t[32][33];
    int tx = threadIdx.x, ty = threadIdx.y, nt = blockIdx.x, kt = blockIdx.y;
#pragma unroll
    for (int i = 0; i < 4; ++i)
        t[ty + 8 * i][tx] = Minv[(kt * 32 + ty + 8 * i) * MDIM + nt * 32 + tx];
    __syncthreads();
#pragma unroll
    for (int i = 0; i < 4; ++i) {
        int n = nt * 32 + ty + 8 * i, k = kt * 32 + tx;
        __nv_bfloat16 h, m, l;
        split3(t[tx][ty + 8 * i], h, m, l);
        g_Bh[n * MDIM + k] = h; g_Bm[n * MDIM + k] = m; g_Bl[n * MDIM + k] = l;
    }
}

__device__ __forceinline__ void mma_step(float acc[4][8], const float* Ar,
                                         const float* Br, int ty, int tx) {
    float4 a4 = *(const float4*)(Ar + ty * 4);
    float4 b0 = *(const float4*)(Br + tx * 8);
    float4 b1 = *(const float4*)(Br + tx * 8 + 4);
    float av[4] = {a4.x, a4.y, a4.z, a4.w};
    float bv[8] = {b0.x, b0.y, b0.z, b0.w, b1.x, b1.y, b1.z, b1.w};
#pragma unroll
    for (int r = 0; r < 4; ++r)
#pragma unroll
        for (int c = 0; c < 8; ++c) acc[r][c] += av[r] * bv[c];
}

__global__ void __launch_bounds__(NTHR, 1)
k_admm(const float* __restrict__ x, const float* __restrict__ w) {
    extern __shared__ char sm[];
    const uint32_t smb = smem_u32(sm);
    const int tid = threadIdx.x;
    const int lane = tid & 31, wrp = tid >> 5;

    int* s_scan = (int*)(sm + SM_SCAN);
    int* s_act = (int*)(sm + SM_ACT);
    float* s_red = (float*)(sm + SM_RED);
    int* s_conv = (int*)(sm + SM_CONV);

    // ===== Phase A: Adotb = x @ w^T (fp32 FFMA, once) + initial E splits =====
    {
        float* As = (float*)(sm + SM_A0);          // [16][68]
        float* Bs = (float*)(sm + SM_A0 + 4608);   // [16][128]
        const int tx = tid & 15, ty = tid >> 4;
        const int ai = tid >> 2, akq = tid & 3;
        int tm = blockIdx.x >> 3, tn = blockIdx.x & 7;
        float acc[4][8];
#pragma unroll
        for (int r = 0; r < 4; ++r)
#pragma unroll
            for (int c = 0; c < 8; ++c) acc[r][c] = 0.f;
        const float* pa = x + (tm * 64 + ai) * NDIM + akq * 4;
        int bm = tid >> 1, bkh = tid & 1;
        const float* pb = w + (tn * 128 + bm) * NDIM + bkh * 8;
        for (int kc = 0; kc < NDIM / 16; ++kc) {
            float4 a = *(const float4*)(pa + kc * 16);
            As[(akq * 4 + 0) * 68 + ai] = a.x;
            As[(akq * 4 + 1) * 68 + ai] = a.y;
            As[(akq * 4 + 2) * 68 + ai] = a.z;
            As[(akq * 4 + 3) * 68 + ai] = a.w;
            float4 b0 = *(const float4*)(pb + kc * 16);
            float4 b1 = *(const float4*)(pb + kc * 16 + 4);
            Bs[(bkh * 8 + 0) * 128 + bm] = b0.x;
            Bs[(bkh * 8 + 1) * 128 + bm] = b0.y;
            Bs[(bkh * 8 + 2) * 128 + bm] = b0.z;
            Bs[(bkh * 8 + 3) * 128 + bm] = b0.w;
            Bs[(bkh * 8 + 4) * 128 + bm] = b1.x;
            Bs[(bkh * 8 + 5) * 128 + bm] = b1.y;
            Bs[(bkh * 8 + 6) * 128 + bm] = b1.z;
            Bs[(bkh * 8 + 7) * 128 + bm] = b1.w;
            __syncthreads();
#pragma unroll
            for (int kk = 0; kk < 16; ++kk)
                mma_step(acc, &As[kk * 68], &Bs[kk * 128], ty, tx);
            __syncthreads();
        }
#pragma unroll
        for (int r = 0; r < 4; ++r) {
            int row = tm * 64 + ty * 4 + r, c0 = tn * 128 + tx * 8;
            float* po = g_Adotb + row * MDIM + c0;
            *(float4*)po = make_float4(acc[r][0], acc[r][1], acc[r][2], acc[r][3]);
            *(float4*)(po + 4) = make_float4(acc[r][4], acc[r][5], acc[r][6], acc[r][7]);
            __align__(16) __nv_bfloat16 hh[8], mm[8], ll[8];
#pragma unroll
            for (int c = 0; c < 8; ++c) split3(acc[r][c], hh[c], mm[c], ll[c]);
            *(uint4*)(g_Eh + row * MDIM + c0) = *(uint4*)hh;
            *(uint4*)(g_Em + row * MDIM + c0) = *(uint4*)mm;
            *(uint4*)(g_El + row * MDIM + c0) = *(uint4*)ll;
        }
    }
    gridbar();

    // ===== ADMM loop =====
    for (int it = 0; it < MAX_ITERS; ++it) {
        // redundant per-CTA ordered compaction of active rows
        int fl[4], cnt = 0;
#pragma unroll
        for (int j = 0; j < 4; ++j) { fl[j] = g_flag[tid * 4 + j]; cnt += (fl[j] == 0); }
        s_scan[tid + 1] = cnt;
        if (tid == 0) s_scan[0] = 0;
        __syncthreads();
        for (int off = 1; off < 256; off <<= 1) {
            int v0 = s_scan[tid + 1];
            int va = (tid + 1 > off) ? s_scan[tid + 1 - off] : 0;
            __syncthreads();
            s_scan[tid + 1] = v0 + va;
            __syncthreads();
        }
        int base = s_scan[tid];
#pragma unroll
        for (int j = 0; j < 4; ++j)
            if (!fl[j]) s_act[base++] = tid * 4 + j;
        __syncthreads();
        int nact = s_scan[256];
        if (nact == 0) break;
        int ntm = (nact + 127) >> 7;

        // ---- HMMA GEMM: xk partials over 6 bf16-split terms ----
        int unit = blockIdx.x & 63, ks = blockIdx.x >> 6;
        int tm = unit >> 3, tn = unit & 7;
        if (tm < ntm) {
            const __nv_bfloat16 *TA[3], *TB[3];
            if (ks == 0) { TA[0] = g_Eh; TA[1] = g_Eh; TA[2] = g_Em;
                           TB[0] = g_Bh; TB[1] = g_Bm; TB[2] = g_Bh; }
            else         { TA[0] = g_Em; TA[1] = g_Eh; TA[2] = g_El;
                           TB[0] = g_Bm; TB[1] = g_Bl; TB[2] = g_Bh; }
            // stage-load mapping: thread covers rows r0, r1; 16B quad per row
            int r0 = tid >> 2, r1 = 64 + (tid >> 2);
            int quad = tid & 3;
            uint32_t d0 = swz((uint32_t)(r0 * 64 + quad * 16));
            uint32_t d1 = swz((uint32_t)(r1 * 64 + quad * 16));
            int gg0 = tm * 128 + r0, gg1 = tm * 128 + r1;
            int a0 = s_act[gg0 < nact ? gg0 : nact - 1] * MDIM + quad * 8;
            int a1 = s_act[gg1 < nact ? gg1 : nact - 1] * MDIM + quad * 8;
            int b0 = (tn * 128 + r0) * MDIM + quad * 8;
            int b1 = (tn * 128 + r1) * MDIM + quad * 8;

            // fragment smem offsets (per lane, fixed)
            int wm = wrp >> 1, wn = wrp & 1;
            int rowa = wm * 32 + (lane & 7) + ((lane >> 3) & 1) * 8;
            int qa = lane >> 4;
            uint32_t offA[2][2];
#pragma unroll
            for (int mi = 0; mi < 2; ++mi)
#pragma unroll
                for (int kk = 0; kk < 2; ++kk)
                    offA[mi][kk] = swz((uint32_t)((rowa + mi * 16) * 64 + (qa + kk * 2) * 16));
            int rowb = wn * 64 + (lane & 7);
            int qb = (lane >> 3) & 1;
            uint32_t offB[8][2];
#pragma unroll
            for (int ni = 0; ni < 8; ++ni)
#pragma unroll
                for (int kk = 0; kk < 2; ++kk)
                    offB[ni][kk] = swz((uint32_t)((rowb + ni * 8) * 64 + (qb + kk * 2) * 16));

            float acc[2][8][4];
#pragma unroll
            for (int mi = 0; mi < 2; ++mi)
#pragma unroll
                for (int ni = 0; ni < 8; ++ni)
#pragma unroll
                    for (int q = 0; q < 4; ++q) acc[mi][ni][q] = 0.f;

            // prologue: stage 0 -> buf 0
            cp16(smb + SM_A0 + d0, TA[0] + a0);
            cp16(smb + SM_A0 + d1, TA[0] + a1);
            cp16(smb + SM_B0 + d0, TB[0] + b0);
            cp16(smb + SM_B0 + d1, TB[0] + b1);
            cp_commit();

            for (int s = 0; s < NSTAGE; ++s) {
                int buf = s & 1;
                if (s + 1 < NSTAGE) {
                    int nb = buf ^ 1;
                    int t2 = (s + 1) >> 5, k2 = ((s + 1) & 31) * 32;
                    uint32_t ab = smb + SM_A0 + nb * 8192;
                    uint32_t bb = smb + SM_B0 + nb * 8192;
                    cp16(ab + d0, TA[t2] + a0 + k2);
                    cp16(ab + d1, TA[t2] + a1 + k2);
                    cp16(bb + d0, TB[t2] + b0 + k2);
                    cp16(bb + d1, TB[t2] + b1 + k2);
                    cp_commit();
                    cp_wait<1>();
                } else {
                    cp_wait<0>();
                }
                __syncthreads();
                uint32_t Ab = smb + SM_A0 + buf * 8192;
                uint32_t Bb = smb + SM_B0 + buf * 8192;
#pragma unroll
                for (int kk = 0; kk < 2; ++kk) {
                    uint32_t af[2][4], bf[8][2];
#pragma unroll
                    for (int mi = 0; mi < 2; ++mi)
                        ldsm_x4(af[mi][0], af[mi][1], af[mi][2], af[mi][3],
                                Ab + offA[mi][kk]);
#pragma unroll
                    for (int ni = 0; ni < 8; ++ni)
                        ldsm_x2t(bf[ni][0], bf[ni][1], Bb + offB[ni][kk]);
#pragma unroll
                    for (int mi = 0; mi < 2; ++mi)
#pragma unroll
                        for (int ni = 0; ni < 8; ++ni)
                            mma16816(acc[mi][ni], af[mi], bf[ni]);
                }
                __syncthreads();
            }

            // epilogue: scatter 32x64 warp fragment to xk partials
            float* dst = ks ? g_xkB : g_xkA;
            int cbase = tn * 128 + wn * 64 + 2 * (lane & 3);
#pragma unroll
            for (int mi = 0; mi < 2; ++mi)
#pragma unroll
                for (int half = 0; half < 2; ++half) {
                    int ridx = wm * 32 + mi * 16 + (lane >> 2) + half * 8;
                    int g = tm * 128 + ridx;
                    if (g < nact) {
                        int row = s_act[g];
                        float* p = dst + row * MDIM + cbase;
#pragma unroll
                        for (int ni = 0; ni < 8; ++ni) {
                            float2 v2 = make_float2(acc[mi][ni][half * 2],
                                                    acc[mi][ni][half * 2 + 1]);
                            *(float2*)(p + ni * 8) = v2;
                        }
                    }
                }
        }
        gridbar();

        // ---- elementwise: softshrink + convergence + next E splits ----
        for (int rr = blockIdx.x; rr < nact; rr += GRID) {
            int row = s_act[rr];
            float4 xa = *((const float4*)(g_xkA + row * MDIM) + tid);
            float4 xb = *((const float4*)(g_xkB + row * MDIM) + tid);
            float4 v4 = *((const float4*)(g_v + row * MDIM) + tid);
            float4 u4 = *((const float4*)(g_u + row * MDIM) + tid);
            float4 a4 = *((const float4*)(g_Adotb + row * MDIM) + tid);
            float xk[4] = {xa.x + xb.x, xa.y + xb.y, xa.z + xb.z, xa.w + xb.w};
            float uo[4] = {u4.x, u4.y, u4.z, u4.w};
            float vo[4] = {v4.x, v4.y, v4.z, v4.w};
            float ao[4] = {a4.x, a4.y, a4.z, a4.w};
            float vn[4], un[4], dx2 = 0.f, x2 = 0.f;
#pragma unroll
            for (int j = 0; j < 4; ++j) {
                float xi = xk[j] + uo[j];
                vn[j] = sshrink(xi);
                un[j] = xi - vn[j];
                float d = vn[j] - vo[j];
                dx2 += d * d;
                x2 += vn[j] * vn[j];
            }
#pragma unroll
            for (int o = 16; o; o >>= 1) {
                dx2 += __shfl_xor_sync(0xffffffffu, dx2, o);
                x2 += __shfl_xor_sync(0xffffffffu, x2, o);
            }
            if (lane == 0) { s_red[wrp] = dx2; s_red[8 + wrp] = x2; }
            __syncthreads();
            if (tid == 0) {
                float dd = 0.f, xx = 0.f;
#pragma unroll
                for (int i = 0; i < 8; ++i) { dd += s_red[i]; xx += s_red[8 + i]; }
                *s_conv = (sqrtf(dd) / sqrtf(xx) < TOLC) ? 1 : 0;  // NaN -> false
            }
            __syncthreads();
            if (*s_conv) {
                *((float4*)(g_vsol + row * MDIM) + tid) =
                    make_float4(vn[0], vn[1], vn[2], vn[3]);
                if (tid == 0) g_flag[row] = 1;
            } else {
                *((float4*)(g_v + row * MDIM) + tid) = make_float4(vn[0], vn[1], vn[2], vn[3]);
                *((float4*)(g_u + row * MDIM) + tid) = make_float4(un[0], un[1], un[2], un[3]);
                __align__(8) __nv_bfloat16 hh[4], mm[4], ll[4];
#pragma unroll
                for (int j = 0; j < 4; ++j)
                    split3(ao[j] + vn[j] - un[j], hh[j], mm[j], ll[j]);
                *(uint2*)(g_Eh + row * MDIM + tid * 4) = *(uint2*)hh;
                *(uint2*)(g_Em + row * MDIM + tid * 4) = *(uint2*)mm;
                *(uint2*)(g_El + row * MDIM + tid * 4) = *(uint2*)ll;
            }
            __syncthreads();
        }
        gridbar();
    }
}

// ---- decode: enc = vsol ; dec = vsol @ w (FFMA, once) ----
__global__ void __launch_bounds__(NTHR, 1) k_decode(const float* __restrict__ w,
                                                    float* __restrict__ enc,
                                                    float* __restrict__ dec) {
    __shared__ __align__(16) float As[16][68];
    __shared__ __align__(16) float Bs[16][128];
    const int tid = threadIdx.x;
    const int tx = tid & 15, ty = tid >> 4;
    const int ai = tid >> 2, akq = tid & 3;
    const int bk = tid >> 4, bj = tid & 15;

    if (enc) {
        const float4* src = (const float4*)g_vsol;
        float4* dst = (float4*)enc;
        for (int i = blockIdx.x * NTHR + tid; i < BATCH * MDIM / 4; i += gridDim.x * NTHR)
            dst[i] = src[i];
    }
    if (!dec) return;

    int tm = blockIdx.x >> 2, tn = blockIdx.x & 3;
    const float* pa = g_vsol + (tm * 64 + ai) * MDIM + akq * 4;
    const float* pb = w + bk * NDIM + tn * 128 + bj * 8;
    float acc[4][8];
#pragma unroll
    for (int r = 0; r < 4; ++r)
#pragma unroll
        for (int c = 0; c < 8; ++c) acc[r][c] = 0.f;
    for (int kc = 0; kc < MDIM / 16; ++kc) {
        float4 a = *(const float4*)(pa + kc * 16);
        As[akq * 4 + 0][ai] = a.x;
        As[akq * 4 + 1][ai] = a.y;
        As[akq * 4 + 2][ai] = a.z;
        As[akq * 4 + 3][ai] = a.w;
        float4 b0 = *(const float4*)(pb + kc * 16 * NDIM);
        float4 b1 = *(const float4*)(pb + kc * 16 * NDIM + 4);
        *(float4*)&Bs[bk][bj * 8] = b0;
        *(float4*)&Bs[bk][bj * 8 + 4] = b1;
        __syncthreads();
#pragma unroll
        for (int kk = 0; kk < 16; ++kk)
            mma_step(acc, &As[kk][0], &Bs[kk][0], ty, tx);
        __syncthreads();
    }
#pragma unroll
    for (int r = 0; r < 4; ++r) {
        float* po = dec + (tm * 64 + ty * 4 + r) * NDIM + tn * 128 + tx * 8;
        *(float4*)po = make_float4(acc[r][0], acc[r][1], acc[r][2], acc[r][3]);
        *(float4*)(po + 4) = make_float4(acc[r][4], acc[r][5], acc[r][6], acc[r][7]);
    }
}

extern "C" void kernel_launch(void* const* d_in, const int* in_sizes, int n_in,
                              void* d_out, int out_size) {
    const float* x = nullptr;
    const float* w = nullptr;
    const float* Minv = nullptr;
    int small[2] = {0, 1}, si = 0;
    for (int i = 0; i < n_in; ++i) {
        if (in_sizes[i] == MDIM * MDIM && !Minv) Minv = (const float*)d_in[i];
        else if (si < 2) small[si++] = i;
    }
    x = (const float*)d_in[small[0]];
    w = (const float*)d_in[small[1]];

    float* out = (float*)d_out;
    float* enc = nullptr;
    float* dec = nullptr;
    if (out_size >= BATCH * MDIM + BATCH * NDIM) { enc = out; dec = out + (size_t)BATCH * MDIM; }
    else if (out_size == BATCH * NDIM) dec = out;
    else enc = out;

    cudaFuncSetAttribute(k_admm, cudaFuncAttributeMaxDynamicSharedMemorySize, SMEM_TOTAL);
    k_init<<<128, 256>>>();
    k_prep<<<dim3(32, 32), dim3(32, 8)>>>(Minv);
    k_admm<<<GRID, NTHR, SMEM_TOTAL>>>(x, w);
    k_decode<<<64, NTHR>>>(w, enc, dec);
}

// round 5
// speedup vs baseline: 3.6661x; 1.8949x over previous
#include <cuda_runtime.h>
#include <cuda_bf16.h>
#include <cstdint>

#define BATCH 1024
#define MDIM  1024
#define NDIM  512
#define LAMBD 0.2f
#define TOLC  1e-4f
#define MAX_ITERS 100
#define GRID  128
#define NTHR  256
#define NSTAGE 24            // per-CTA stages: half of (3 terms x 16 k64-chunks)

// dynamic smem layout (bytes)
#define SM_RED   64
#define SM_CONV  192
#define SM_SCAN  256        // 257 ints
#define SM_ACT   2560       // 1024 ints
#define SM_A0    8192       // A stage buffers 2 x 16KB
#define SM_B0    40960      // B stage buffers 2 x 16KB
#define SMEM_TOTAL 73728

__device__ __align__(16) float g_Adotb[BATCH * MDIM];
__device__ __align__(16) float g_v[BATCH * MDIM];
__device__ __align__(16) float g_u[BATCH * MDIM];
__device__ __align__(16) float g_vsol[BATCH * MDIM];
__device__ __align__(16) float g_xkA[BATCH * MDIM];
__device__ __align__(16) float g_xkB[BATCH * MDIM];
__device__ __align__(16) __nv_bfloat16 g_Eh[BATCH * MDIM];
__device__ __align__(16) __nv_bfloat16 g_Em[BATCH * MDIM];
__device__ __align__(16) __nv_bfloat16 g_Bh[MDIM * MDIM];   // B[n][k] = Minv[k][n]
__device__ __align__(16) __nv_bfloat16 g_Bm[MDIM * MDIM];
__device__ int g_flag[BATCH];
__device__ unsigned g_count, g_gen;

// ---------- helpers ----------
__device__ __forceinline__ uint32_t smem_u32(const void* p) {
    uint32_t a;
    asm("{ .reg .u64 t; cvta.to.shared.u64 t, %1; cvt.u32.u64 %0, t; }" : "=r"(a) : "l"(p));
    return a;
}
// SW128 swizzle for 128B-stride rows
__device__ __forceinline__ uint32_t swz(uint32_t o) { return o ^ ((o >> 3) & 0x70); }

__device__ __forceinline__ void cp16(uint32_t d, const void* s) {
    asm volatile("cp.async.cg.shared.global [%0], [%1], 16;" :: "r"(d), "l"(s));
}
__device__ __forceinline__ void cp_commit() { asm volatile("cp.async.commit_group;" ::: "memory"); }
template <int N> __device__ __forceinline__ void cp_wait() {
    asm volatile("cp.async.wait_group %0;" :: "n"(N) : "memory");
}
__device__ __forceinline__ void ldsm_x4(uint32_t& r0, uint32_t& r1, uint32_t& r2,
                                        uint32_t& r3, uint32_t a) {
    asm volatile("ldmatrix.sync.aligned.m8n8.x4.shared.b16 {%0,%1,%2,%3}, [%4];"
                 : "=r"(r0), "=r"(r1), "=r"(r2), "=r"(r3) : "r"(a));
}
__device__ __forceinline__ void ldsm_x2t(uint32_t& r0, uint32_t& r1, uint32_t a) {
    asm volatile("ldmatrix.sync.aligned.m8n8.x2.trans.shared.b16 {%0,%1}, [%2];"
                 : "=r"(r0), "=r"(r1) : "r"(a));
}
__device__ __forceinline__ void mma16816(float d[4], const uint32_t a[4], const uint32_t b[2]) {
    asm volatile(
        "mma.sync.aligned.m16n8k16.row.col.f32.bf16.bf16.f32 "
        "{%0,%1,%2,%3}, {%4,%5,%6,%7}, {%8,%9}, {%0,%1,%2,%3};"
        : "+f"(d[0]), "+f"(d[1]), "+f"(d[2]), "+f"(d[3])
        : "r"(a[0]), "r"(a[1]), "r"(a[2]), "r"(a[3]), "r"(b[0]), "r"(b[1]));
}

__device__ __forceinline__ void gridbar() {
    __syncthreads();
    if (threadIdx.x == 0) {
        unsigned my = atomicAdd(&g_gen, 0u);
        __threadfence();
        if (atomicAdd(&g_count, 1u) == GRID - 1u) {
            atomicExch(&g_count, 0u);
            __threadfence();
            atomicAdd(&g_gen, 1u);
        } else {
            while (atomicAdd(&g_gen, 0u) == my) __nanosleep(64);
        }
        __threadfence();
    }
    __syncthreads();
}

__device__ __forceinline__ float sshrink(float x) {
    return x > LAMBD ? x - LAMBD : (x < -LAMBD ? x + LAMBD : 0.f);
}
__device__ __forceinline__ void split2(float a, __nv_bfloat16& h, __nv_bfloat16& m) {
    h = __float2bfloat16(a);
    m = __float2bfloat16(a - __bfloat162float(h));
}

__global__ void k_init() {
    int tid = blockIdx.x * blockDim.x + threadIdx.x, nt = gridDim.x * blockDim.x;
    float4 z = make_float4(0.f, 0.f, 0.f, 0.f);
    for (int i = tid; i < BATCH * MDIM / 4; i += nt) {
        ((float4*)g_v)[i] = z; ((float4*)g_u)[i] = z; ((float4*)g_vsol)[i] = z;
    }
    for (int i = tid; i < BATCH; i += nt) g_flag[i] = 0;
    if (tid == 0) { g_count = 0u; g_gen = 0u; }
}

// transpose + 2-way bf16 split of Minv
__global__ void k_prep(const float* __restrict__ Minv) {
    __shared__ float t[32][33];
    int tx = threadIdx.x, ty = threadIdx.y, nt = blockIdx.x, kt = blockIdx.y;
#pragma unroll
    for (int i = 0; i < 4; ++i)
        t[ty + 8 * i][tx] = Minv[(kt * 32 + ty + 8 * i) * MDIM + nt * 32 + tx];
    __syncthreads();
#pragma unroll
    for (int i = 0; i < 4; ++i) {
        int n = nt * 32 + ty + 8 * i, k = kt * 32 + tx;
        __nv_bfloat16 h, m;
        split2(t[tx][ty + 8 * i], h, m);
        g_Bh[n * MDIM + k] = h; g_Bm[n * MDIM + k] = m;
    }
}

__device__ __forceinline__ void mma_step(float acc[4][8], const float* Ar,
                                         const float* Br, int ty, int tx) {
    float4 a4 = *(const float4*)(Ar + ty * 4);
    float4 b0 = *(const float4*)(Br + tx * 8);
    float4 b1 = *(const float4*)(Br + tx * 8 + 4);
    float av[4] = {a4.x, a4.y, a4.z, a4.w};
    float bv[8] = {b0.x, b0.y, b0.z, b0.w, b1.x, b1.y, b1.z, b1.w};
#pragma unroll
    for (int r = 0; r < 4; ++r)
#pragma unroll
        for (int c = 0; c < 8; ++c) acc[r][c] += av[r] * bv[c];
}

__global__ void __launch_bounds__(NTHR, 1)
k_admm(const float* __restrict__ x, const float* __restrict__ w) {
    extern __shared__ char sm[];
    const uint32_t smb = smem_u32(sm);
    const int tid = threadIdx.x;
    const int lane = tid & 31, wrp = tid >> 5;

    int* s_scan = (int*)(sm + SM_SCAN);
    int* s_act = (int*)(sm + SM_ACT);
    float* s_red = (float*)(sm + SM_RED);
    int* s_conv = (int*)(sm + SM_CONV);

    // ===== Phase A: Adotb = x @ w^T (fp32 FFMA, once) + initial E splits =====
    {
        float* As = (float*)(sm + SM_A0);          // [16][68]
        float* Bs = (float*)(sm + SM_A0 + 4608);   // [16][128]
        const int tx = tid & 15, ty = tid >> 4;
        const int ai = tid >> 2, akq = tid & 3;
        int tm = blockIdx.x >> 3, tn = blockIdx.x & 7;
        float acc[4][8];
#pragma unroll
        for (int r = 0; r < 4; ++r)
#pragma unroll
            for (int c = 0; c < 8; ++c) acc[r][c] = 0.f;
        const float* pa = x + (tm * 64 + ai) * NDIM + akq * 4;
        int bm = tid >> 1, bkh = tid & 1;
        const float* pb = w + (tn * 128 + bm) * NDIM + bkh * 8;
        for (int kc = 0; kc < NDIM / 16; ++kc) {
            float4 a = *(const float4*)(pa + kc * 16);
            As[(akq * 4 + 0) * 68 + ai] = a.x;
            As[(akq * 4 + 1) * 68 + ai] = a.y;
            As[(akq * 4 + 2) * 68 + ai] = a.z;
            As[(akq * 4 + 3) * 68 + ai] = a.w;
            float4 b0 = *(const float4*)(pb + kc * 16);
            float4 b1 = *(const float4*)(pb + kc * 16 + 4);
            Bs[(bkh * 8 + 0) * 128 + bm] = b0.x;
            Bs[(bkh * 8 + 1) * 128 + bm] = b0.y;
            Bs[(bkh * 8 + 2) * 128 + bm] = b0.z;
            Bs[(bkh * 8 + 3) * 128 + bm] = b0.w;
            Bs[(bkh * 8 + 4) * 128 + bm] = b1.x;
            Bs[(bkh * 8 + 5) * 128 + bm] = b1.y;
            Bs[(bkh * 8 + 6) * 128 + bm] = b1.z;
            Bs[(bkh * 8 + 7) * 128 + bm] = b1.w;
            __syncthreads();
#pragma unroll
            for (int kk = 0; kk < 16; ++kk)
                mma_step(acc, &As[kk * 68], &Bs[kk * 128], ty, tx);
            __syncthreads();
        }
#pragma unroll
        for (int r = 0; r < 4; ++r) {
            int row = tm * 64 + ty * 4 + r, c0 = tn * 128 + tx * 8;
            float* po = g_Adotb + row * MDIM + c0;
            *(float4*)po = make_float4(acc[r][0], acc[r][1], acc[r][2], acc[r][3]);
            *(float4*)(po + 4) = make_float4(acc[r][4], acc[r][5], acc[r][6], acc[r][7]);
            __align__(16) __nv_bfloat16 hh[8], mm[8];
#pragma unroll
            for (int c = 0; c < 8; ++c) split2(acc[r][c], hh[c], mm[c]);
            *(uint4*)(g_Eh + row * MDIM + c0) = *(uint4*)hh;
            *(uint4*)(g_Em + row * MDIM + c0) = *(uint4*)mm;
        }
    }
    gridbar();

    // ===== ADMM loop =====
    for (int it = 0; it < MAX_ITERS; ++it) {
        // redundant per-CTA ordered compaction of active rows
        int fl[4], cnt = 0;
#pragma unroll
        for (int j = 0; j < 4; ++j) { fl[j] = g_flag[tid * 4 + j]; cnt += (fl[j] == 0); }
        s_scan[tid + 1] = cnt;
        if (tid == 0) s_scan[0] = 0;
        __syncthreads();
        for (int off = 1; off < 256; off <<= 1) {
            int v0 = s_scan[tid + 1];
            int va = (tid + 1 > off) ? s_scan[tid + 1 - off] : 0;
            __syncthreads();
            s_scan[tid + 1] = v0 + va;
            __syncthreads();
        }
        int base = s_scan[tid];
#pragma unroll
        for (int j = 0; j < 4; ++j)
            if (!fl[j]) s_act[base++] = tid * 4 + j;
        __syncthreads();
        int nact = s_scan[256];
        if (nact == 0) break;
        int ntm = (nact + 127) >> 7;

        // ---- HMMA GEMM: xk partials over 3 bf16-split terms (hh, hm, mh) ----
        // global stage g = ks*24 + s in [0,48): term = g>>4, k0 = (g&15)*64
        int unit = blockIdx.x & 63, ks = blockIdx.x >> 6;
        int tm = unit >> 3, tn = unit & 7;
        if (tm < ntm) {
            const __nv_bfloat16* TA[3] = {g_Eh, g_Eh, g_Em};
            const __nv_bfloat16* TB[3] = {g_Bh, g_Bm, g_Bh};
            int gbase = ks * NSTAGE;
            // stage-load mapping: 4 chunks/thread/operand, rows of 128B
            uint32_t dsw[4];
            int aoff[4], boff[4];
#pragma unroll
            for (int c = 0; c < 4; ++c) {
                int idx = tid + 256 * c;
                int rw = idx >> 3, q = idx & 7;
                dsw[c] = swz((uint32_t)(rw * 128 + q * 16));
                int g = tm * 128 + rw;
                aoff[c] = s_act[g < nact ? g : nact - 1] * MDIM + q * 8;
                boff[c] = (tn * 128 + rw) * MDIM + q * 8;
            }
            // ldmatrix base offsets (kk handled by XOR of kk<<5)
            int wm = wrp >> 1, wn = wrp & 1;
            int rowa = wm * 32 + (lane & 7) + ((lane >> 3) & 1) * 8;
            int qa = lane >> 4;
            uint32_t offA[2];
#pragma unroll
            for (int mi = 0; mi < 2; ++mi)
                offA[mi] = swz((uint32_t)((rowa + mi * 16) * 128 + qa * 16));
            int rowb = wn * 64 + (lane & 7);
            int qb = (lane >> 3) & 1;
            uint32_t offB[8];
#pragma unroll
            for (int ni = 0; ni < 8; ++ni)
                offB[ni] = swz((uint32_t)((rowb + ni * 8) * 128 + qb * 16));

            float acc[2][8][4];
#pragma unroll
            for (int mi = 0; mi < 2; ++mi)
#pragma unroll
                for (int ni = 0; ni < 8; ++ni)
#pragma unroll
                    for (int q = 0; q < 4; ++q) acc[mi][ni][q] = 0.f;

            // prologue: stage gbase -> buf 0
            {
                int t2 = gbase >> 4, k2 = (gbase & 15) * 64;
#pragma unroll
                for (int c = 0; c < 4; ++c) {
                    cp16(smb + SM_A0 + dsw[c], TA[t2] + aoff[c] + k2);
                    cp16(smb + SM_B0 + dsw[c], TB[t2] + boff[c] + k2);
                }
                cp_commit();
            }
            for (int s = 0; s < NSTAGE; ++s) {
                int buf = s & 1;
                if (s + 1 < NSTAGE) {
                    int nb = buf ^ 1;
                    int gg = gbase + s + 1;
                    int t2 = gg >> 4, k2 = (gg & 15) * 64;
                    uint32_t ab = smb + SM_A0 + nb * 16384;
                    uint32_t bb = smb + SM_B0 + nb * 16384;
#pragma unroll
                    for (int c = 0; c < 4; ++c) {
                        cp16(ab + dsw[c], TA[t2] + aoff[c] + k2);
                        cp16(bb + dsw[c], TB[t2] + boff[c] + k2);
                    }
                    cp_commit();
                    cp_wait<1>();
                } else {
                    cp_wait<0>();
                }
                __syncthreads();
                uint32_t Ab = smb + SM_A0 + buf * 16384;
                uint32_t Bb = smb + SM_B0 + buf * 16384;
#pragma unroll
                for (int kk = 0; kk < 4; ++kk) {
                    uint32_t kx = (uint32_t)(kk << 5);
                    uint32_t af[2][4], bf[8][2];
#pragma unroll
                    for (int mi = 0; mi < 2; ++mi)
                        ldsm_x4(af[mi][0], af[mi][1], af[mi][2], af[mi][3],
                                Ab + (offA[mi] ^ kx));
#pragma unroll
                    for (int ni = 0; ni < 8; ++ni)
                        ldsm_x2t(bf[ni][0], bf[ni][1], Bb + (offB[ni] ^ kx));
#pragma unroll
                    for (int mi = 0; mi < 2; ++mi)
#pragma unroll
                        for (int ni = 0; ni < 8; ++ni)
                            mma16816(acc[mi][ni], af[mi], bf[ni]);
                }
                __syncthreads();
            }

            // epilogue: scatter 32x64 warp fragment to xk partials
            float* dst = ks ? g_xkB : g_xkA;
            int cbase = tn * 128 + wn * 64 + 2 * (lane & 3);
#pragma unroll
            for (int mi = 0; mi < 2; ++mi)
#pragma unroll
                for (int half = 0; half < 2; ++half) {
                    int ridx = wm * 32 + mi * 16 + (lane >> 2) + half * 8;
                    int g = tm * 128 + ridx;
                    if (g < nact) {
                        int row = s_act[g];
                        float* p = dst + row * MDIM + cbase;
#pragma unroll
                        for (int ni = 0; ni < 8; ++ni) {
                            float2 v2 = make_float2(acc[mi][ni][half * 2],
                                                    acc[mi][ni][half * 2 + 1]);
                            *(float2*)(p + ni * 8) = v2;
                        }
                    }
                }
        }
        gridbar();

        // ---- elementwise: softshrink + convergence + next E splits ----
        for (int rr = blockIdx.x; rr < nact; rr += GRID) {
            int row = s_act[rr];
            float4 xa = *((const float4*)(g_xkA + row * MDIM) + tid);
            float4 xb = *((const float4*)(g_xkB + row * MDIM) + tid);
            float4 v4 = *((const float4*)(g_v + row * MDIM) + tid);
            float4 u4 = *((const float4*)(g_u + row * MDIM) + tid);
            float4 a4 = *((const float4*)(g_Adotb + row * MDIM) + tid);
            float xk[4] = {xa.x + xb.x, xa.y + xb.y, xa.z + xb.z, xa.w + xb.w};
            float uo[4] = {u4.x, u4.y, u4.z, u4.w};
            float vo[4] = {v4.x, v4.y, v4.z, v4.w};
            float ao[4] = {a4.x, a4.y, a4.z, a4.w};
            float vn[4], un[4], dx2 = 0.f, x2 = 0.f;
#pragma unroll
            for (int j = 0; j < 4; ++j) {
                float xi = xk[j] + uo[j];
                vn[j] = sshrink(xi);
                un[j] = xi - vn[j];
                float d = vn[j] - vo[j];
                dx2 += d * d;
                x2 += vn[j] * vn[j];
            }
#pragma unroll
            for (int o = 16; o; o >>= 1) {
                dx2 += __shfl_xor_sync(0xffffffffu, dx2, o);
                x2 += __shfl_xor_sync(0xffffffffu, x2, o);
            }
            if (lane == 0) { s_red[wrp] = dx2; s_red[8 + wrp] = x2; }
            __syncthreads();
            if (tid == 0) {
                float dd = 0.f, xx = 0.f;
#pragma unroll
                for (int i = 0; i < 8; ++i) { dd += s_red[i]; xx += s_red[8 + i]; }
                *s_conv = (sqrtf(dd) / sqrtf(xx) < TOLC) ? 1 : 0;  // NaN -> false
            }
            __syncthreads();
            if (*s_conv) {
                *((float4*)(g_vsol + row * MDIM) + tid) =
                    make_float4(vn[0], vn[1], vn[2], vn[3]);
                if (tid == 0) g_flag[row] = 1;
            } else {
                *((float4*)(g_v + row * MDIM) + tid) = make_float4(vn[0], vn[1], vn[2], vn[3]);
                *((float4*)(g_u + row * MDIM) + tid) = make_float4(un[0], un[1], un[2], un[3]);
                __align__(8) __nv_bfloat16 hh[4], mm[4];
#pragma unroll
                for (int j = 0; j < 4; ++j)
                    split2(ao[j] + vn[j] - un[j], hh[j], mm[j]);
                *(uint2*)(g_Eh + row * MDIM + tid * 4) = *(uint2*)hh;
                *(uint2*)(g_Em + row * MDIM + tid * 4) = *(uint2*)mm;
            }
            __syncthreads();
        }
        gridbar();
    }
}

// ---- decode: enc = vsol ; dec = vsol @ w (FFMA, 128 CTAs of 64x64) ----
__global__ void __launch_bounds__(NTHR, 1) k_decode(const float* __restrict__ w,
                                                    float* __restrict__ enc,
                                                    float* __restrict__ dec) {
    __shared__ __align__(16) float As[16][68];
    __shared__ __align__(16) float Bs[16][64];
    const int tid = threadIdx.x;
    const int tx = tid & 15, ty = tid >> 4;
    const int ai = tid >> 2, akq = tid & 3;
    const int bk = tid >> 4, bj = tid & 15;

    if (enc) {
        const float4* src = (const float4*)g_vsol;
        float4* dst = (float4*)enc;
        for (int i = blockIdx.x * NTHR + tid; i < BATCH * MDIM / 4; i += gridDim.x * NTHR)
            dst[i] = src[i];
    }
    if (!dec) return;

    int tm = blockIdx.x >> 3, tn = blockIdx.x & 7;
    const float* pa = g_vsol + (tm * 64 + ai) * MDIM + akq * 4;
    const float* pb = w + bk * NDIM + tn * 64 + bj * 4;
    float acc[4][4];
#pragma unroll
    for (int r = 0; r < 4; ++r)
#pragma unroll
        for (int c = 0; c < 4; ++c) acc[r][c] = 0.f;
    for (int kc = 0; kc < MDIM / 16; ++kc) {
        float4 a = *(const float4*)(pa + kc * 16);
        As[akq * 4 + 0][ai] = a.x;
        As[akq * 4 + 1][ai] = a.y;
        As[akq * 4 + 2][ai] = a.z;
        As[akq * 4 + 3][ai] = a.w;
        float4 b0 = *(const float4*)(pb + kc * 16 * NDIM);
        *(float4*)&Bs[bk][bj * 4] = b0;
        __syncthreads();
#pragma unroll
        for (int kk = 0; kk < 16; ++kk) {
            float4 a4 = *(const float4*)(&As[kk][ty * 4]);
            float4 b4 = *(const float4*)(&Bs[kk][tx * 4]);
            float av[4] = {a4.x, a4.y, a4.z, a4.w};
            float bv[4] = {b4.x, b4.y, b4.z, b4.w};
#pragma unroll
            for (int r = 0; r < 4; ++r)
#pragma unroll
                for (int c = 0; c < 4; ++c) acc[r][c] += av[r] * bv[c];
        }
        __syncthreads();
    }
#pragma unroll
    for (int r = 0; r < 4; ++r) {
        float* po = dec + (tm * 64 + ty * 4 + r) * NDIM + tn * 64 + tx * 4;
        *(float4*)po = make_float4(acc[r][0], acc[r][1], acc[r][2], acc[r][3]);
    }
}

extern "C" void kernel_launch(void* const* d_in, const int* in_sizes, int n_in,
                              void* d_out, int out_size) {
    const float* x = nullptr;
    const float* w = nullptr;
    const float* Minv = nullptr;
    int small[2] = {0, 1}, si = 0;
    for (int i = 0; i < n_in; ++i) {
        if (in_sizes[i] == MDIM * MDIM && !Minv) Minv = (const float*)d_in[i];
        else if (si < 2) small[si++] = i;
    }
    x = (const float*)d_in[small[0]];
    w = (const float*)d_in[small[1]];

    float* out = (float*)d_out;
    float* enc = nullptr;
    float* dec = nullptr;
    if (out_size >= BATCH * MDIM + BATCH * NDIM) { enc = out; dec = out + (size_t)BATCH * MDIM; }
    else if (out_size == BATCH * NDIM) dec = out;
    else enc = out;

    cudaFuncSetAttribute(k_admm, cudaFuncAttributeMaxDynamicSharedMemorySize, SMEM_TOTAL);
    k_init<<<128, 256>>>();
    k_prep<<<dim3(32, 32), dim3(32, 8)>>>(Minv);
    k_admm<<<GRID, NTHR, SMEM_TOTAL>>>(x, w);
    k_decode<<<GRID, NTHR>>>(w, enc, dec);
}

// round 7
// speedup vs baseline: 3.8159x; 1.0409x over previous
#include <cuda_runtime.h>
#include <cuda_bf16.h>
#include <cstdint>

#define BATCH 1024
#define MDIM  1024
#define NDIM  512
#define LAMBD 0.2f
#define TOLC  1e-4f
#define MAX_ITERS 100
#define GRID  128
#define NTHR  256
#define NSTAGE 24            // per-CTA stages: half of (3 terms x 16 k64-chunks)
#define PIPE  4

// dynamic smem layout (bytes)
#define SM_RED   64
#define SM_CONV  192        // 2 ints
#define SM_SCAN  256        // 257 ints
#define SM_ACT   2560       // 1024 ints
#define SM_A0    8192       // A stage buffers 4 x 16KB
#define SM_B0    73728      // B stage buffers 4 x 16KB
#define SMEM_TOTAL 139264

__device__ __align__(16) float g_Adotb[BATCH * MDIM];
__device__ __align__(16) float g_v[BATCH * MDIM];
__device__ __align__(16) float g_u[BATCH * MDIM];
__device__ __align__(16) float g_vsol[BATCH * MDIM];
__device__ __align__(16) float g_xkA[BATCH * MDIM];
__device__ __align__(16) float g_xkB[BATCH * MDIM];
__device__ __align__(16) __nv_bfloat16 g_Eh[BATCH * MDIM];
__device__ __align__(16) __nv_bfloat16 g_Em[BATCH * MDIM];
__device__ __align__(16) __nv_bfloat16 g_Vh[BATCH * MDIM];   // splits of vsol
__device__ __align__(16) __nv_bfloat16 g_Vm[BATCH * MDIM];
__device__ __align__(16) __nv_bfloat16 g_Bh[MDIM * MDIM];    // B[n][k] = Minv[k][n]
__device__ __align__(16) __nv_bfloat16 g_Bm[MDIM * MDIM];
__device__ __align__(16) __nv_bfloat16 g_Wh[NDIM * MDIM];    // W[n][k] = w[k][n]
__device__ __align__(16) __nv_bfloat16 g_Wm[NDIM * MDIM];
__device__ int g_flag[BATCH];
__device__ unsigned g_count, g_gen;

// ---------- helpers ----------
__device__ __forceinline__ uint32_t smem_u32(const void* p) {
    uint32_t a;
    asm("{ .reg .u64 t; cvta.to.shared.u64 t, %1; cvt.u32.u64 %0, t; }" : "=r"(a) : "l"(p));
    return a;
}
__device__ __forceinline__ uint32_t swz(uint32_t o) { return o ^ ((o >> 3) & 0x70); }

__device__ __forceinline__ void cp16(uint32_t d, const void* s) {
    asm volatile("cp.async.cg.shared.global [%0], [%1], 16;" :: "r"(d), "l"(s));
}
__device__ __forceinline__ void cp_commit() { asm volatile("cp.async.commit_group;" ::: "memory"); }
template <int N> __device__ __forceinline__ void cp_wait() {
    asm volatile("cp.async.wait_group %0;" :: "n"(N) : "memory");
}
__device__ __forceinline__ void ldsm_x4(uint32_t& r0, uint32_t& r1, uint32_t& r2,
                                        uint32_t& r3, uint32_t a) {
    asm volatile("ldmatrix.sync.aligned.m8n8.x4.shared.b16 {%0,%1,%2,%3}, [%4];"
                 : "=r"(r0), "=r"(r1), "=r"(r2), "=r"(r3) : "r"(a));
}
__device__ __forceinline__ void ldsm_x2t(uint32_t& r0, uint32_t& r1, uint32_t a) {
    asm volatile("ldmatrix.sync.aligned.m8n8.x2.trans.shared.b16 {%0,%1}, [%2];"
                 : "=r"(r0), "=r"(r1) : "r"(a));
}
__device__ __forceinline__ void mma16816(float d[4], const uint32_t a[4], const uint32_t b[2]) {
    asm volatile(
        "mma.sync.aligned.m16n8k16.row.col.f32.bf16.bf16.f32 "
        "{%0,%1,%2,%3}, {%4,%5,%6,%7}, {%8,%9}, {%0,%1,%2,%3};"
        : "+f"(d[0]), "+f"(d[1]), "+f"(d[2]), "+f"(d[3])
        : "r"(a[0]), "r"(a[1]), "r"(a[2]), "r"(a[3]), "r"(b[0]), "r"(b[1]));
}

__device__ __forceinline__ void gridbar() {
    __syncthreads();
    if (threadIdx.x == 0) {
        unsigned my = *(volatile unsigned*)&g_gen;
        __threadfence();
        if (atomicAdd(&g_count, 1u) == GRID - 1u) {
            atomicExch(&g_count, 0u);
            __threadfence();
            atomicAdd(&g_gen, 1u);
        } else {
            while (*(volatile unsigned*)&g_gen == my) {}
        }
        __threadfence();
    }
    __syncthreads();
}

__device__ __forceinline__ float sshrink(float x) {
    return x > LAMBD ? x - LAMBD : (x < -LAMBD ? x + LAMBD : 0.f);
}
__device__ __forceinline__ void split2(float a, __nv_bfloat16& h, __nv_bfloat16& m) {
    h = __float2bfloat16(a);
    m = __float2bfloat16(a - __bfloat162float(h));
}

__global__ void k_init() {
    int tid = blockIdx.x * blockDim.x + threadIdx.x, nt = gridDim.x * blockDim.x;
    float4 z = make_float4(0.f, 0.f, 0.f, 0.f);
    for (int i = tid; i < BATCH * MDIM / 4; i += nt) {
        ((float4*)g_v)[i] = z; ((float4*)g_u)[i] = z; ((float4*)g_vsol)[i] = z;
    }
    uint4 z4 = make_uint4(0u, 0u, 0u, 0u);
    for (int i = tid; i < BATCH * MDIM / 8; i += nt) {
        ((uint4*)g_Vh)[i] = z4; ((uint4*)g_Vm)[i] = z4;
    }
    for (int i = tid; i < BATCH; i += nt) g_flag[i] = 0;
    if (tid == 0) { g_count = 0u; g_gen = 0u; }
}

// transpose + 2-way bf16 split of Minv (1024x1024)
__global__ void k_prep(const float* __restrict__ Minv) {
    __shared__ float t[32][33];
    int tx = threadIdx.x, ty = threadIdx.y, nt = blockIdx.x, kt = blockIdx.y;
#pragma unroll
    for (int i = 0; i < 4; ++i)
        t[ty + 8 * i][tx] = Minv[(kt * 32 + ty + 8 * i) * MDIM + nt * 32 + tx];
    __syncthreads();
#pragma unroll
    for (int i = 0; i < 4; ++i) {
        int n = nt * 32 + ty + 8 * i, k = kt * 32 + tx;
        __nv_bfloat16 h, m;
        split2(t[tx][ty + 8 * i], h, m);
        g_Bh[n * MDIM + k] = h; g_Bm[n * MDIM + k] = m;
    }
}

// transpose + 2-way bf16 split of w (1024x512) -> W[n][k]
__global__ void k_prepw(const float* __restrict__ w) {
    __shared__ float t[32][33];
    int tx = threadIdx.x, ty = threadIdx.y, nt = blockIdx.x, kt = blockIdx.y;
#pragma unroll
    for (int i = 0; i < 4; ++i)
        t[ty + 8 * i][tx] = w[(kt * 32 + ty + 8 * i) * NDIM + nt * 32 + tx];
    __syncthreads();
#pragma unroll
    for (int i = 0; i < 4; ++i) {
        int n = nt * 32 + ty + 8 * i, k = kt * 32 + tx;
        __nv_bfloat16 h, m;
        split2(t[tx][ty + 8 * i], h, m);
        g_Wh[n * MDIM + k] = h; g_Wm[n * MDIM + k] = m;
    }
}

__device__ __forceinline__ void mma_step(float acc[4][8], const float* Ar,
                                         const float* Br, int ty, int tx) {
    float4 a4 = *(const float4*)(Ar + ty * 4);
    float4 b0 = *(const float4*)(Br + tx * 8);
    float4 b1 = *(const float4*)(Br + tx * 8 + 4);
    float av[4] = {a4.x, a4.y, a4.z, a4.w};
    float bv[8] = {b0.x, b0.y, b0.z, b0.w, b1.x, b1.y, b1.z, b1.w};
#pragma unroll
    for (int r = 0; r < 4; ++r)
#pragma unroll
        for (int c = 0; c < 8; ++c) acc[r][c] += av[r] * bv[c];
}

// shared HMMA mainloop: 128x128 tile, NSTAGE k64 stages, 4-deep cp.async pipe,
// one __syncthreads per stage. Schedule: global stage g -> term g>>4, k0 (g&15)*64.
__device__ __forceinline__ void hmma_tile(
    uint32_t smb, int gbase,
    const __nv_bfloat16* TA0, const __nv_bfloat16* TA1, const __nv_bfloat16* TA2,
    const __nv_bfloat16* TB0, const __nv_bfloat16* TB1, const __nv_bfloat16* TB2,
    const int aoff[4], const int boff[4], const uint32_t dsw[4],
    const uint32_t offA[2], const uint32_t offB[8], float acc[2][8][4]) {
    const __nv_bfloat16* TA[3] = {TA0, TA1, TA2};
    const __nv_bfloat16* TB[3] = {TB0, TB1, TB2};
#pragma unroll
    for (int p = 0; p < PIPE - 1; ++p) {
        int g = gbase + p, t2 = g >> 4, k2 = (g & 15) * 64;
        uint32_t ab = smb + SM_A0 + p * 16384, bb = smb + SM_B0 + p * 16384;
#pragma unroll
        for (int c = 0; c < 4; ++c) {
            cp16(ab + dsw[c], TA[t2] + aoff[c] + k2);
            cp16(bb + dsw[c], TB[t2] + boff[c] + k2);
        }
        cp_commit();
    }
    for (int s = 0; s < NSTAGE; ++s) {
        cp_wait<PIPE - 2>();
        __syncthreads();
        if (s + PIPE - 1 < NSTAGE) {
            int nb = (s + PIPE - 1) & (PIPE - 1);
            int g = gbase + s + PIPE - 1, t2 = g >> 4, k2 = (g & 15) * 64;
            uint32_t ab = smb + SM_A0 + nb * 16384, bb = smb + SM_B0 + nb * 16384;
#pragma unroll
            for (int c = 0; c < 4; ++c) {
                cp16(ab + dsw[c], TA[t2] + aoff[c] + k2);
                cp16(bb + dsw[c], TB[t2] + boff[c] + k2);
            }
        }
        cp_commit();   // always commit (possibly empty) to keep wait-count semantics
        int buf = s & (PIPE - 1);
        uint32_t Ab = smb + SM_A0 + buf * 16384;
        uint32_t Bb = smb + SM_B0 + buf * 16384;
#pragma unroll
        for (int kk = 0; kk < 4; ++kk) {
            uint32_t kx = (uint32_t)(kk << 5);
            uint32_t af[2][4], bf[8][2];
#pragma unroll
            for (int mi = 0; mi < 2; ++mi)
                ldsm_x4(af[mi][0], af[mi][1], af[mi][2], af[mi][3], Ab + (offA[mi] ^ kx));
#pragma unroll
            for (int ni = 0; ni < 8; ++ni)
                ldsm_x2t(bf[ni][0], bf[ni][1], Bb + (offB[ni] ^ kx));
#pragma unroll
            for (int mi = 0; mi < 2; ++mi)
#pragma unroll
                for (int ni = 0; ni < 8; ++ni)
                    mma16816(acc[mi][ni], af[mi], bf[ni]);
        }
    }
    cp_wait<0>();
}

__global__ void __launch_bounds__(NTHR, 1)
k_admm(const float* __restrict__ x, const float* __restrict__ w) {
    extern __shared__ char sm[];
    const uint32_t smb = smem_u32(sm);
    const int tid = threadIdx.x;
    const int lane = tid & 31, wrp = tid >> 5;

    int* s_scan = (int*)(sm + SM_SCAN);
    int* s_act = (int*)(sm + SM_ACT);
    float* s_red = (float*)(sm + SM_RED);
    int* s_conv = (int*)(sm + SM_CONV);

    // ===== Phase A: Adotb = x @ w^T (fp32 FFMA, once) + initial E splits =====
    {
        float* As = (float*)(sm + SM_A0);          // [16][68]
        float* Bs = (float*)(sm + SM_A0 + 4608);   // [16][128]
        const int tx = tid & 15, ty = tid >> 4;
        const int ai = tid >> 2, akq = tid & 3;
        int tm = blockIdx.x >> 3, tn = blockIdx.x & 7;
        float acc[4][8];
#pragma unroll
        for (int r = 0; r < 4; ++r)
#pragma unroll
            for (int c = 0; c < 8; ++c) acc[r][c] = 0.f;
        const float* pa = x + (tm * 64 + ai) * NDIM + akq * 4;
        int bm = tid >> 1, bkh = tid & 1;
        const float* pb = w + (tn * 128 + bm) * NDIM + bkh * 8;
        for (int kc = 0; kc < NDIM / 16; ++kc) {
            float4 a = *(const float4*)(pa + kc * 16);
            As[(akq * 4 + 0) * 68 + ai] = a.x;
            As[(akq * 4 + 1) * 68 + ai] = a.y;
            As[(akq * 4 + 2) * 68 + ai] = a.z;
            As[(akq * 4 + 3) * 68 + ai] = a.w;
            float4 b0 = *(const float4*)(pb + kc * 16);
            float4 b1 = *(const float4*)(pb + kc * 16 + 4);
            Bs[(bkh * 8 + 0) * 128 + bm] = b0.x;
            Bs[(bkh * 8 + 1) * 128 + bm] = b0.y;
            Bs[(bkh * 8 + 2) * 128 + bm] = b0.z;
            Bs[(bkh * 8 + 3) * 128 + bm] = b0.w;
            Bs[(bkh * 8 + 4) * 128 + bm] = b1.x;
            Bs[(bkh * 8 + 5) * 128 + bm] = b1.y;
            Bs[(bkh * 8 + 6) * 128 + bm] = b1.z;
            Bs[(bkh * 8 + 7) * 128 + bm] = b1.w;
            __syncthreads();
#pragma unroll
            for (int kk = 0; kk < 16; ++kk)
                mma_step(acc, &As[kk * 68], &Bs[kk * 128], ty, tx);
            __syncthreads();
        }
#pragma unroll
        for (int r = 0; r < 4; ++r) {
            int row = tm * 64 + ty * 4 + r, c0 = tn * 128 + tx * 8;
            float* po = g_Adotb + row * MDIM + c0;
            *(float4*)po = make_float4(acc[r][0], acc[r][1], acc[r][2], acc[r][3]);
            *(float4*)(po + 4) = make_float4(acc[r][4], acc[r][5], acc[r][6], acc[r][7]);
            __align__(16) __nv_bfloat16 hh[8], mm[8];
#pragma unroll
            for (int c = 0; c < 8; ++c) split2(acc[r][c], hh[c], mm[c]);
            *(uint4*)(g_Eh + row * MDIM + c0) = *(uint4*)hh;
            *(uint4*)(g_Em + row * MDIM + c0) = *(uint4*)mm;
        }
    }
    gridbar();

    // ===== ADMM loop =====
    for (int it = 0; it < MAX_ITERS; ++it) {
        // redundant per-CTA ordered compaction of active rows
        int fl[4], cnt = 0;
#pragma unroll
        for (int j = 0; j < 4; ++j) { fl[j] = g_flag[tid * 4 + j]; cnt += (fl[j] == 0); }
        s_scan[tid + 1] = cnt;
        if (tid == 0) s_scan[0] = 0;
        __syncthreads();
        for (int off = 1; off < 256; off <<= 1) {
            int v0 = s_scan[tid + 1];
            int va = (tid + 1 > off) ? s_scan[tid + 1 - off] : 0;
            __syncthreads();
            s_scan[tid + 1] = v0 + va;
            __syncthreads();
        }
        int base = s_scan[tid];
#pragma unroll
        for (int j = 0; j < 4; ++j)
            if (!fl[j]) s_act[base++] = tid * 4 + j;
        __syncthreads();
        int nact = s_scan[256];
        if (nact == 0) break;
        int ntm = (nact + 127) >> 7;

        // ---- HMMA GEMM: xk partials over 3 bf16-split terms (hh, hm, mh) ----
        int unit = blockIdx.x & 63, ks = blockIdx.x >> 6;
        int tm = unit >> 3, tn = unit & 7;
        if (tm < ntm) {
            uint32_t dsw[4];
            int aoff[4], boff[4];
#pragma unroll
            for (int c = 0; c < 4; ++c) {
                int idx = tid + 256 * c;
                int rw = idx >> 3, q = idx & 7;
                dsw[c] = swz((uint32_t)(rw * 128 + q * 16));
                int g = tm * 128 + rw;
                aoff[c] = s_act[g < nact ? g : nact - 1] * MDIM + q * 8;
                boff[c] = (tn * 128 + rw) * MDIM + q * 8;
            }
            int wm = wrp >> 1, wn = wrp & 1;
            int rowa = wm * 32 + (lane & 7) + ((lane >> 3) & 1) * 8;
            int qa = lane >> 4;
            uint32_t offA[2];
#pragma unroll
            for (int mi = 0; mi < 2; ++mi)
                offA[mi] = swz((uint32_t)((rowa + mi * 16) * 128 + qa * 16));
            int rowb = wn * 64 + (lane & 7);
            int qb = (lane >> 3) & 1;
            uint32_t offB[8];
#pragma unroll
            for (int ni = 0; ni < 8; ++ni)
                offB[ni] = swz((uint32_t)((rowb + ni * 8) * 128 + qb * 16));

            float acc[2][8][4];
#pragma unroll
            for (int mi = 0; mi < 2; ++mi)
#pragma unroll
                for (int ni = 0; ni < 8; ++ni)
#pragma unroll
                    for (int q = 0; q < 4; ++q) acc[mi][ni][q] = 0.f;

            hmma_tile(smb, ks * NSTAGE, g_Eh, g_Eh, g_Em, g_Bh, g_Bm, g_Bh,
                      aoff, boff, dsw, offA, offB, acc);

            float* dst = ks ? g_xkB : g_xkA;
            int cbase = tn * 128 + wn * 64 + 2 * (lane & 3);
#pragma unroll
            for (int mi = 0; mi < 2; ++mi)
#pragma unroll
                for (int half = 0; half < 2; ++half) {
                    int ridx = wm * 32 + mi * 16 + (lane >> 2) + half * 8;
                    int g = tm * 128 + ridx;
                    if (g < nact) {
                        int row = s_act[g];
                        float* p = dst + row * MDIM + cbase;
#pragma unroll
                        for (int ni = 0; ni < 8; ++ni) {
                            float2 v2 = make_float2(acc[mi][ni][half * 2],
                                                    acc[mi][ni][half * 2 + 1]);
                            *(float2*)(p + ni * 8) = v2;
                        }
                    }
                }
        }
        gridbar();

        // ---- elementwise: 2 rows per CTA pass; softshrink + conv + next splits ----
        for (int rr = blockIdx.x * 2; rr < nact; rr += GRID * 2) {
            int half = tid >> 7;
            int ridx = rr + half;
            bool valid = ridx < nact;
            int row = s_act[valid ? ridx : nact - 1];
            int t = tid & 127;
            int eb = row * MDIM + t * 8;
            float4 xa0 = *(const float4*)(g_xkA + eb);
            float4 xa1 = *(const float4*)(g_xkA + eb + 4);
            float4 xb0 = *(const float4*)(g_xkB + eb);
            float4 xb1 = *(const float4*)(g_xkB + eb + 4);
            float4 v0 = *(const float4*)(g_v + eb);
            float4 v1 = *(const float4*)(g_v + eb + 4);
            float4 u0 = *(const float4*)(g_u + eb);
            float4 u1 = *(const float4*)(g_u + eb + 4);
            float4 a0 = *(const float4*)(g_Adotb + eb);
            float4 a1 = *(const float4*)(g_Adotb + eb + 4);
            float xk[8] = {xa0.x + xb0.x, xa0.y + xb0.y, xa0.z + xb0.z, xa0.w + xb0.w,
                           xa1.x + xb1.x, xa1.y + xb1.y, xa1.z + xb1.z, xa1.w + xb1.w};
            float vo[8] = {v0.x, v0.y, v0.z, v0.w, v1.x, v1.y, v1.z, v1.w};
            float uo[8] = {u0.x, u0.y, u0.z, u0.w, u1.x, u1.y, u1.z, u1.w};
            float ao[8] = {a0.x, a0.y, a0.z, a0.w, a1.x, a1.y, a1.z, a1.w};
            float vn[8], un[8], dx2 = 0.f, x2 = 0.f;
#pragma unroll
            for (int j = 0; j < 8; ++j) {
                float xi = xk[j] + uo[j];
                vn[j] = sshrink(xi);
                un[j] = xi - vn[j];
                float d = vn[j] - vo[j];
                dx2 += d * d;
                x2 += vn[j] * vn[j];
            }
#pragma unroll
            for (int o = 16; o; o >>= 1) {
                dx2 += __shfl_xor_sync(0xffffffffu, dx2, o);
                x2 += __shfl_xor_sync(0xffffffffu, x2, o);
            }
            if (lane == 0) { s_red[wrp] = dx2; s_red[8 + wrp] = x2; }
            __syncthreads();
            if (t == 0) {
                float dd = 0.f, xx = 0.f;
#pragma unroll
                for (int i = 0; i < 4; ++i) {
                    dd += s_red[half * 4 + i];
                    xx += s_red[8 + half * 4 + i];
                }
                s_conv[half] = (sqrtf(dd) / sqrtf(xx) < TOLC) ? 1 : 0;  // NaN -> false
            }
            __syncthreads();
            if (valid) {
                if (s_conv[half]) {
                    *(float4*)(g_vsol + eb) = make_float4(vn[0], vn[1], vn[2], vn[3]);
                    *(float4*)(g_vsol + eb + 4) = make_float4(vn[4], vn[5], vn[6], vn[7]);
                    __align__(16) __nv_bfloat16 hh[8], mm[8];
#pragma unroll
                    for (int j = 0; j < 8; ++j) split2(vn[j], hh[j], mm[j]);
                    *(uint4*)(g_Vh + eb) = *(uint4*)hh;
                    *(uint4*)(g_Vm + eb) = *(uint4*)mm;
                    if (t == 0) g_flag[row] = 1;
                } else {
                    *(float4*)(g_v + eb) = make_float4(vn[0], vn[1], vn[2], vn[3]);
                    *(float4*)(g_v + eb + 4) = make_float4(vn[4], vn[5], vn[6], vn[7]);
                    *(float4*)(g_u + eb) = make_float4(un[0], un[1], un[2], un[3]);
                    *(float4*)(g_u + eb + 4) = make_float4(un[4], un[5], un[6], un[7]);
                    __align__(16) __nv_bfloat16 hh[8], mm[8];
#pragma unroll
                    for (int j = 0; j < 8; ++j)
                        split2(ao[j] + vn[j] - un[j], hh[j], mm[j]);
                    *(uint4*)(g_Eh + eb) = *(uint4*)hh;
                    *(uint4*)(g_Em + eb) = *(uint4*)mm;
                }
            }
            __syncthreads();
        }
        gridbar();
    }
}

// ---- decode: CTAs 0-63 HMMA partials of vsol @ w; CTAs 64-127 copy enc ----
__global__ void __launch_bounds__(NTHR, 1) k_decode(float* __restrict__ enc,
                                                    const float* __restrict__ dec) {
    extern __shared__ char sm[];
    const uint32_t smb = smem_u32(sm);
    const int tid = threadIdx.x;
    const int lane = tid & 31, wrp = tid >> 5;
    int bid = blockIdx.x;

    if (bid >= 64) {
        if (enc) {
            const float4* src = (const float4*)g_vsol;
            float4* dst = (float4*)enc;
            for (int i = (bid - 64) * NTHR + tid; i < BATCH * MDIM / 4; i += 64 * NTHR)
                dst[i] = src[i];
        }
        return;
    }
    if (!dec) return;

    int ks = bid >> 5, unit = bid & 31;
    int tm = unit >> 2, tn = unit & 3;
    uint32_t dsw[4];
    int aoff[4], boff[4];
#pragma unroll
    for (int c = 0; c < 4; ++c) {
        int idx = tid + 256 * c;
        int rw = idx >> 3, q = idx & 7;
        dsw[c] = swz((uint32_t)(rw * 128 + q * 16));
        aoff[c] = (tm * 128 + rw) * MDIM + q * 8;
        boff[c] = (tn * 128 + rw) * MDIM + q * 8;
    }
    int wm = wrp >> 1, wn = wrp & 1;
    int rowa = wm * 32 + (lane & 7) + ((lane >> 3) & 1) * 8;
    int qa = lane >> 4;
    uint32_t offA[2];
#pragma unroll
    for (int mi = 0; mi < 2; ++mi)
        offA[mi] = swz((uint32_t)((rowa + mi * 16) * 128 + qa * 16));
    int rowb = wn * 64 + (lane & 7);
    int qb = (lane >> 3) & 1;
    uint32_t offB[8];
#pragma unroll
    for (int ni = 0; ni < 8; ++ni)
        offB[ni] = swz((uint32_t)((rowb + ni * 8) * 128 + qb * 16));

    float acc[2][8][4];
#pragma unroll
    for (int mi = 0; mi < 2; ++mi)
#pragma unroll
        for (int ni = 0; ni < 8; ++ni)
#pragma unroll
            for (int q = 0; q < 4; ++q) acc[mi][ni][q] = 0.f;

    hmma_tile(smb, ks * NSTAGE, g_Vh, g_Vh, g_Vm, g_Wh, g_Wm, g_Wh,
              aoff, boff, dsw, offA, offB, acc);

    float* dst = ks ? g_xkB : g_xkA;
    int cbase = tn * 128 + wn * 64 + 2 * (lane & 3);
#pragma unroll
    for (int mi = 0; mi < 2; ++mi)
#pragma unroll
        for (int half = 0; half < 2; ++half) {
            int ridx = wm * 32 + mi * 16 + (lane >> 2) + half * 8;
            int row = tm * 128 + ridx;
            float* p = dst + row * NDIM + cbase;
#pragma unroll
            for (int ni = 0; ni < 8; ++ni) {
                float2 v2 = make_float2(acc[mi][ni][half * 2], acc[mi][ni][half * 2 + 1]);
                *(float2*)(p + ni * 8) = v2;
            }
        }
}

__global__ void k_sum(float* __restrict__ dec) {
    int tid = blockIdx.x * blockDim.x + threadIdx.x, nt = gridDim.x * blockDim.x;
    const float4* pa = (const float4*)g_xkA;
    const float4* pb = (const float4*)g_xkB;
    float4* po = (float4*)dec;
    for (int i = tid; i < BATCH * NDIM / 4; i += nt) {
        float4 a = pa[i], b = pb[i];
        po[i] = make_float4(a.x + b.x, a.y + b.y, a.z + b.z, a.w + b.w);
    }
}

extern "C" void kernel_launch(void* const* d_in, const int* in_sizes, int n_in,
                              void* d_out, int out_size) {
    const float* x = nullptr;
    const float* w = nullptr;
    const float* Minv = nullptr;
    int small[2] = {0, 1}, si = 0;
    for (int i = 0; i < n_in; ++i) {
        if (in_sizes[i] == MDIM * MDIM && !Minv) Minv = (const float*)d_in[i];
        else if (si < 2) small[si++] = i;
    }
    x = (const float*)d_in[small[0]];
    w = (const float*)d_in[small[1]];

    float* out = (float*)d_out;
    float* enc = nullptr;
    float* dec = nullptr;
    if (out_size >= BATCH * MDIM + BATCH * NDIM) { enc = out; dec = out + (size_t)BATCH * MDIM; }
    else if (out_size == BATCH * NDIM) dec = out;
    else enc = out;

    cudaFuncSetAttribute(k_admm, cudaFuncAttributeMaxDynamicSharedMemorySize, SMEM_TOTAL);
    cudaFuncSetAttribute(k_decode, cudaFuncAttributeMaxDynamicSharedMemorySize, SMEM_TOTAL);
    k_init<<<128, 256>>>();
    k_prep<<<dim3(32, 32), dim3(32, 8)>>>(Minv);
    k_prepw<<<dim3(16, 32), dim3(32, 8)>>>(w);
    k_admm<<<GRID, NTHR, SMEM_TOTAL>>>(x, w);
    k_decode<<<GRID, NTHR, SMEM_TOTAL>>>(enc, dec);
    if (dec) k_sum<<<64, 256>>>(dec);
}

// round 8
// speedup vs baseline: 3.8310x; 1.0040x over previous
#include <cuda_runtime.h>
#include <cuda_bf16.h>
#include <cstdint>

#define BATCH 1024
#define MDIM  1024
#define NDIM  512
#define LAMBD 0.2f
#define TOLC  1e-4f
#define MAX_ITERS 100
#define GRID  128
#define NTHR  512
#define NSTAGE 24            // per-CTA stages: half of (3 terms x 16 k64-chunks)
#define PIPE  4

// dynamic smem layout (bytes)
#define SM_RED   64         // 32 floats
#define SM_CONV  192        // 4 ints
#define SM_SCAN  256        // 513 ints
#define SM_ACT   2560       // 1024 ints
#define SM_A0    8192       // A stage buffers 4 x 16KB
#define SM_B0    73728      // B stage buffers 4 x 16KB
#define SMEM_TOTAL 139264

__device__ __align__(16) float g_Adotb[BATCH * MDIM];
__device__ __align__(16) float g_v[BATCH * MDIM];
__device__ __align__(16) float g_u[BATCH * MDIM];
__device__ __align__(16) float g_vsol[BATCH * MDIM];
__device__ __align__(16) float g_xkA[BATCH * MDIM];
__device__ __align__(16) float g_xkB[BATCH * MDIM];
__device__ __align__(16) __nv_bfloat16 g_Eh[BATCH * MDIM];
__device__ __align__(16) __nv_bfloat16 g_Em[BATCH * MDIM];
__device__ __align__(16) __nv_bfloat16 g_Vh[BATCH * MDIM];   // splits of vsol
__device__ __align__(16) __nv_bfloat16 g_Vm[BATCH * MDIM];
__device__ __align__(16) __nv_bfloat16 g_Bh[MDIM * MDIM];    // B[n][k] = Minv[k][n]
__device__ __align__(16) __nv_bfloat16 g_Bm[MDIM * MDIM];
__device__ __align__(16) __nv_bfloat16 g_Wh[NDIM * MDIM];    // W[n][k] = w[k][n]
__device__ __align__(16) __nv_bfloat16 g_Wm[NDIM * MDIM];
__device__ int g_flag[BATCH];
__device__ unsigned g_count, g_gen;

// ---------- helpers ----------
__device__ __forceinline__ uint32_t smem_u32(const void* p) {
    uint32_t a;
    asm("{ .reg .u64 t; cvta.to.shared.u64 t, %1; cvt.u32.u64 %0, t; }" : "=r"(a) : "l"(p));
    return a;
}
__device__ __forceinline__ uint32_t swz(uint32_t o) { return o ^ ((o >> 3) & 0x70); }

__device__ __forceinline__ void cp16(uint32_t d, const void* s) {
    asm volatile("cp.async.cg.shared.global [%0], [%1], 16;" :: "r"(d), "l"(s));
}
__device__ __forceinline__ void cp_commit() { asm volatile("cp.async.commit_group;" ::: "memory"); }
template <int N> __device__ __forceinline__ void cp_wait() {
    asm volatile("cp.async.wait_group %0;" :: "n"(N) : "memory");
}
__device__ __forceinline__ void ldsm_x4(uint32_t& r0, uint32_t& r1, uint32_t& r2,
                                        uint32_t& r3, uint32_t a) {
    asm volatile("ldmatrix.sync.aligned.m8n8.x4.shared.b16 {%0,%1,%2,%3}, [%4];"
                 : "=r"(r0), "=r"(r1), "=r"(r2), "=r"(r3) : "r"(a));
}
__device__ __forceinline__ void ldsm_x2t(uint32_t& r0, uint32_t& r1, uint32_t a) {
    asm volatile("ldmatrix.sync.aligned.m8n8.x2.trans.shared.b16 {%0,%1}, [%2];"
                 : "=r"(r0), "=r"(r1) : "r"(a));
}
__device__ __forceinline__ void mma16816(float d[4], const uint32_t a[4], const uint32_t b[2]) {
    asm volatile(
        "mma.sync.aligned.m16n8k16.row.col.f32.bf16.bf16.f32 "
        "{%0,%1,%2,%3}, {%4,%5,%6,%7}, {%8,%9}, {%0,%1,%2,%3};"
        : "+f"(d[0]), "+f"(d[1]), "+f"(d[2]), "+f"(d[3])
        : "r"(a[0]), "r"(a[1]), "r"(a[2]), "r"(a[3]), "r"(b[0]), "r"(b[1]));
}

__device__ __forceinline__ void gridbar() {
    __syncthreads();
    if (threadIdx.x == 0) {
        unsigned my = *(volatile unsigned*)&g_gen;
        __threadfence();
        if (atomicAdd(&g_count, 1u) == GRID - 1u) {
            atomicExch(&g_count, 0u);
            __threadfence();
            atomicAdd(&g_gen, 1u);
        } else {
            while (*(volatile unsigned*)&g_gen == my) {}
        }
        __threadfence();
    }
    __syncthreads();
}

__device__ __forceinline__ float sshrink(float x) {
    return x > LAMBD ? x - LAMBD : (x < -LAMBD ? x + LAMBD : 0.f);
}
__device__ __forceinline__ void split2(float a, __nv_bfloat16& h, __nv_bfloat16& m) {
    h = __float2bfloat16(a);
    m = __float2bfloat16(a - __bfloat162float(h));
}

__global__ void k_init() {
    int tid = blockIdx.x * blockDim.x + threadIdx.x, nt = gridDim.x * blockDim.x;
    float4 z = make_float4(0.f, 0.f, 0.f, 0.f);
    for (int i = tid; i < BATCH * MDIM / 4; i += nt) {
        ((float4*)g_v)[i] = z; ((float4*)g_u)[i] = z; ((float4*)g_vsol)[i] = z;
    }
    uint4 z4 = make_uint4(0u, 0u, 0u, 0u);
    for (int i = tid; i < BATCH * MDIM / 8; i += nt) {
        ((uint4*)g_Vh)[i] = z4; ((uint4*)g_Vm)[i] = z4;
    }
    for (int i = tid; i < BATCH; i += nt) g_flag[i] = 0;
    if (tid == 0) { g_count = 0u; g_gen = 0u; }
}

// transpose + 2-way bf16 split of Minv (1024x1024)
__global__ void k_prep(const float* __restrict__ Minv) {
    __shared__ float t[32][33];
    int tx = threadIdx.x, ty = threadIdx.y, nt = blockIdx.x, kt = blockIdx.y;
#pragma unroll
    for (int i = 0; i < 4; ++i)
        t[ty + 8 * i][tx] = Minv[(kt * 32 + ty + 8 * i) * MDIM + nt * 32 + tx];
    __syncthreads();
#pragma unroll
    for (int i = 0; i < 4; ++i) {
        int n = nt * 32 + ty + 8 * i, k = kt * 32 + tx;
        __nv_bfloat16 h, m;
        split2(t[tx][ty + 8 * i], h, m);
        g_Bh[n * MDIM + k] = h; g_Bm[n * MDIM + k] = m;
    }
}

// transpose + 2-way bf16 split of w (1024x512) -> W[n][k]
__global__ void k_prepw(const float* __restrict__ w) {
    __shared__ float t[32][33];
    int tx = threadIdx.x, ty = threadIdx.y, nt = blockIdx.x, kt = blockIdx.y;
#pragma unroll
    for (int i = 0; i < 4; ++i)
        t[ty + 8 * i][tx] = w[(kt * 32 + ty + 8 * i) * NDIM + nt * 32 + tx];
    __syncthreads();
#pragma unroll
    for (int i = 0; i < 4; ++i) {
        int n = nt * 32 + ty + 8 * i, k = kt * 32 + tx;
        __nv_bfloat16 h, m;
        split2(t[tx][ty + 8 * i], h, m);
        g_Wh[n * MDIM + k] = h; g_Wm[n * MDIM + k] = m;
    }
}

// shared HMMA mainloop: 128x128 tile, 512 threads (16 warps, 32x32 warp tiles),
// NSTAGE k64 stages, 4-deep cp.async pipe, one __syncthreads per stage.
__device__ __forceinline__ void hmma_tile(
    uint32_t smb, int gbase,
    const __nv_bfloat16* TA0, const __nv_bfloat16* TA1, const __nv_bfloat16* TA2,
    const __nv_bfloat16* TB0, const __nv_bfloat16* TB1, const __nv_bfloat16* TB2,
    const int aoff[2], const int boff[2], const uint32_t dsw[2],
    const uint32_t offA[2], const uint32_t offB[4], float acc[2][4][4]) {
    const __nv_bfloat16* TA[3] = {TA0, TA1, TA2};
    const __nv_bfloat16* TB[3] = {TB0, TB1, TB2};
#pragma unroll
    for (int p = 0; p < PIPE - 1; ++p) {
        int g = gbase + p, t2 = g >> 4, k2 = (g & 15) * 64;
        uint32_t ab = smb + SM_A0 + p * 16384, bb = smb + SM_B0 + p * 16384;
#pragma unroll
        for (int c = 0; c < 2; ++c) {
            cp16(ab + dsw[c], TA[t2] + aoff[c] + k2);
            cp16(bb + dsw[c], TB[t2] + boff[c] + k2);
        }
        cp_commit();
    }
    for (int s = 0; s < NSTAGE; ++s) {
        cp_wait<PIPE - 2>();
        __syncthreads();
        if (s + PIPE - 1 < NSTAGE) {
            int nb = (s + PIPE - 1) & (PIPE - 1);
            int g = gbase + s + PIPE - 1, t2 = g >> 4, k2 = (g & 15) * 64;
            uint32_t ab = smb + SM_A0 + nb * 16384, bb = smb + SM_B0 + nb * 16384;
#pragma unroll
            for (int c = 0; c < 2; ++c) {
                cp16(ab + dsw[c], TA[t2] + aoff[c] + k2);
                cp16(bb + dsw[c], TB[t2] + boff[c] + k2);
            }
        }
        cp_commit();   // always commit (possibly empty) to keep wait-count semantics
        int buf = s & (PIPE - 1);
        uint32_t Ab = smb + SM_A0 + buf * 16384;
        uint32_t Bb = smb + SM_B0 + buf * 16384;
#pragma unroll
        for (int kk = 0; kk < 4; ++kk) {
            uint32_t kx = (uint32_t)(kk << 5);
            uint32_t af[2][4], bf[4][2];
#pragma unroll
            for (int mi = 0; mi < 2; ++mi)
                ldsm_x4(af[mi][0], af[mi][1], af[mi][2], af[mi][3], Ab + (offA[mi] ^ kx));
#pragma unroll
            for (int ni = 0; ni < 4; ++ni)
                ldsm_x2t(bf[ni][0], bf[ni][1], Bb + (offB[ni] ^ kx));
#pragma unroll
            for (int mi = 0; mi < 2; ++mi)
#pragma unroll
                for (int ni = 0; ni < 4; ++ni)
                    mma16816(acc[mi][ni], af[mi], bf[ni]);
        }
    }
    cp_wait<0>();
}

__global__ void __launch_bounds__(NTHR, 1)
k_admm(const float* __restrict__ x, const float* __restrict__ w) {
    extern __shared__ char sm[];
    const uint32_t smb = smem_u32(sm);
    const int tid = threadIdx.x;
    const int lane = tid & 31, wrp = tid >> 5;

    int* s_scan = (int*)(sm + SM_SCAN);
    int* s_act = (int*)(sm + SM_ACT);
    float* s_red = (float*)(sm + SM_RED);
    int* s_conv = (int*)(sm + SM_CONV);

    // ===== Phase A: Adotb = x @ w^T (fp32 FFMA, once) + initial E splits =====
    {
        float* As = (float*)(sm + SM_A0);          // [16][68]
        float* Bs = (float*)(sm + SM_A0 + 4608);   // [16][128]
        const int tx = tid & 15, ty = tid >> 4;    // ty 0..31
        int tm = blockIdx.x >> 3, tn = blockIdx.x & 7;   // 64x128 tile
        float acc[2][8];
#pragma unroll
        for (int r = 0; r < 2; ++r)
#pragma unroll
            for (int c = 0; c < 8; ++c) acc[r][c] = 0.f;
        const int ai = tid >> 2, akq = tid & 3;          // A loads: tid<256
        const float* pa = x + (tm * 64 + ai) * NDIM + akq * 4;
        const int bm = tid >> 2, bkq = tid & 3;          // B loads: all 512
        const float* pb = w + (tn * 128 + bm) * NDIM + bkq * 4;
        for (int kc = 0; kc < NDIM / 16; ++kc) {
            if (tid < 256) {
                float4 a = *(const float4*)(pa + kc * 16);
                As[(akq * 4 + 0) * 68 + ai] = a.x;
                As[(akq * 4 + 1) * 68 + ai] = a.y;
                As[(akq * 4 + 2) * 68 + ai] = a.z;
                As[(akq * 4 + 3) * 68 + ai] = a.w;
            }
            float4 b0 = *(const float4*)(pb + kc * 16);
            Bs[(bkq * 4 + 0) * 128 + bm] = b0.x;
            Bs[(bkq * 4 + 1) * 128 + bm] = b0.y;
            Bs[(bkq * 4 + 2) * 128 + bm] = b0.z;
            Bs[(bkq * 4 + 3) * 128 + bm] = b0.w;
            __syncthreads();
#pragma unroll
            for (int kk = 0; kk < 16; ++kk) {
                float2 a2 = *(const float2*)(&As[kk * 68 + ty * 2]);
                float4 b0v = *(const float4*)(&Bs[kk * 128 + tx * 8]);
                float4 b1v = *(const float4*)(&Bs[kk * 128 + tx * 8 + 4]);
                float av[2] = {a2.x, a2.y};
                float bv[8] = {b0v.x, b0v.y, b0v.z, b0v.w, b1v.x, b1v.y, b1v.z, b1v.w};
#pragma unroll
                for (int r = 0; r < 2; ++r)
#pragma unroll
                    for (int c = 0; c < 8; ++c) acc[r][c] += av[r] * bv[c];
            }
            __syncthreads();
        }
#pragma unroll
        for (int r = 0; r < 2; ++r) {
            int row = tm * 64 + ty * 2 + r, c0 = tn * 128 + tx * 8;
            float* po = g_Adotb + row * MDIM + c0;
            *(float4*)po = make_float4(acc[r][0], acc[r][1], acc[r][2], acc[r][3]);
            *(float4*)(po + 4) = make_float4(acc[r][4], acc[r][5], acc[r][6], acc[r][7]);
            __align__(16) __nv_bfloat16 hh[8], mm[8];
#pragma unroll
            for (int c = 0; c < 8; ++c) split2(acc[r][c], hh[c], mm[c]);
            *(uint4*)(g_Eh + row * MDIM + c0) = *(uint4*)hh;
            *(uint4*)(g_Em + row * MDIM + c0) = *(uint4*)mm;
        }
    }
    gridbar();

    // ===== ADMM loop =====
    for (int it = 0; it < MAX_ITERS; ++it) {
        // redundant per-CTA ordered compaction of active rows (2 flags/thread)
        int fl[2], cnt = 0;
#pragma unroll
        for (int j = 0; j < 2; ++j) { fl[j] = g_flag[tid * 2 + j]; cnt += (fl[j] == 0); }
        s_scan[tid + 1] = cnt;
        if (tid == 0) s_scan[0] = 0;
        __syncthreads();
        for (int off = 1; off < 512; off <<= 1) {
            int v0 = s_scan[tid + 1];
            int va = (tid + 1 > off) ? s_scan[tid + 1 - off] : 0;
            __syncthreads();
            s_scan[tid + 1] = v0 + va;
            __syncthreads();
        }
        int base = s_scan[tid];
#pragma unroll
        for (int j = 0; j < 2; ++j)
            if (!fl[j]) s_act[base++] = tid * 2 + j;
        __syncthreads();
        int nact = s_scan[512];
        if (nact == 0) break;
        int ntm = (nact + 127) >> 7;

        // ---- HMMA GEMM: xk partials over 3 bf16-split terms (hh, hm, mh) ----
        int unit = blockIdx.x & 63, ks = blockIdx.x >> 6;
        int tm = unit >> 3, tn = unit & 7;
        if (tm < ntm) {
            uint32_t dsw[2];
            int aoff[2], boff[2];
#pragma unroll
            for (int c = 0; c < 2; ++c) {
                int idx = tid + 512 * c;
                int rw = idx >> 3, q = idx & 7;
                dsw[c] = swz((uint32_t)(rw * 128 + q * 16));
                int g = tm * 128 + rw;
                aoff[c] = s_act[g < nact ? g : nact - 1] * MDIM + q * 8;
                boff[c] = (tn * 128 + rw) * MDIM + q * 8;
            }
            int wm = wrp >> 2, wn = wrp & 3;
            int rowa = wm * 32 + (lane & 7) + ((lane >> 3) & 1) * 8;
            int qa = lane >> 4;
            uint32_t offA[2];
#pragma unroll
            for (int mi = 0; mi < 2; ++mi)
                offA[mi] = swz((uint32_t)((rowa + mi * 16) * 128 + qa * 16));
            int rowb = wn * 32 + (lane & 7);
            int qb = (lane >> 3) & 1;
            uint32_t offB[4];
#pragma unroll
            for (int ni = 0; ni < 4; ++ni)
                offB[ni] = swz((uint32_t)((rowb + ni * 8) * 128 + qb * 16));

            float acc[2][4][4];
#pragma unroll
            for (int mi = 0; mi < 2; ++mi)
#pragma unroll
                for (int ni = 0; ni < 4; ++ni)
#pragma unroll
                    for (int q = 0; q < 4; ++q) acc[mi][ni][q] = 0.f;

            hmma_tile(smb, ks * NSTAGE, g_Eh, g_Eh, g_Em, g_Bh, g_Bm, g_Bh,
                      aoff, boff, dsw, offA, offB, acc);

            float* dst = ks ? g_xkB : g_xkA;
            int cbase = tn * 128 + wn * 32 + 2 * (lane & 3);
#pragma unroll
            for (int mi = 0; mi < 2; ++mi)
#pragma unroll
                for (int half = 0; half < 2; ++half) {
                    int ridx = wm * 32 + mi * 16 + (lane >> 2) + half * 8;
                    int g = tm * 128 + ridx;
                    if (g < nact) {
                        int row = s_act[g];
                        float* p = dst + row * MDIM + cbase;
#pragma unroll
                        for (int ni = 0; ni < 4; ++ni) {
                            float2 v2 = make_float2(acc[mi][ni][half * 2],
                                                    acc[mi][ni][half * 2 + 1]);
                            *(float2*)(p + ni * 8) = v2;
                        }
                    }
                }
        }
        gridbar();

        // ---- elementwise: 4 rows per CTA pass; softshrink + conv + next splits ----
        for (int rr = blockIdx.x * 4; rr < nact; rr += GRID * 4) {
            int quarter = tid >> 7;
            int ridx = rr + quarter;
            bool valid = ridx < nact;
            int row = s_act[valid ? ridx : nact - 1];
            int t = tid & 127;
            int eb = row * MDIM + t * 8;
            float4 xa0 = *(const float4*)(g_xkA + eb);
            float4 xa1 = *(const float4*)(g_xkA + eb + 4);
            float4 xb0 = *(const float4*)(g_xkB + eb);
            float4 xb1 = *(const float4*)(g_xkB + eb + 4);
            float4 v0 = *(const float4*)(g_v + eb);
            float4 v1 = *(const float4*)(g_v + eb + 4);
            float4 u0 = *(const float4*)(g_u + eb);
            float4 u1 = *(const float4*)(g_u + eb + 4);
            float4 a0 = *(const float4*)(g_Adotb + eb);
            float4 a1 = *(const float4*)(g_Adotb + eb + 4);
            float xk[8] = {xa0.x + xb0.x, xa0.y + xb0.y, xa0.z + xb0.z, xa0.w + xb0.w,
                           xa1.x + xb1.x, xa1.y + xb1.y, xa1.z + xb1.z, xa1.w + xb1.w};
            float vo[8] = {v0.x, v0.y, v0.z, v0.w, v1.x, v1.y, v1.z, v1.w};
            float uo[8] = {u0.x, u0.y, u0.z, u0.w, u1.x, u1.y, u1.z, u1.w};
            float ao[8] = {a0.x, a0.y, a0.z, a0.w, a1.x, a1.y, a1.z, a1.w};
            float vn[8], un[8], dx2 = 0.f, x2 = 0.f;
#pragma unroll
            for (int j = 0; j < 8; ++j) {
                float xi = xk[j] + uo[j];
                vn[j] = sshrink(xi);
                un[j] = xi - vn[j];
                float d = vn[j] - vo[j];
                dx2 += d * d;
                x2 += vn[j] * vn[j];
            }
#pragma unroll
            for (int o = 16; o; o >>= 1) {
                dx2 += __shfl_xor_sync(0xffffffffu, dx2, o);
                x2 += __shfl_xor_sync(0xffffffffu, x2, o);
            }
            if (lane == 0) { s_red[wrp] = dx2; s_red[16 + wrp] = x2; }
            __syncthreads();
            if (t == 0) {
                float dd = 0.f, xx = 0.f;
#pragma unroll
                for (int i = 0; i < 4; ++i) {
                    dd += s_red[quarter * 4 + i];
                    xx += s_red[16 + quarter * 4 + i];
                }
                s_conv[quarter] = (sqrtf(dd) / sqrtf(xx) < TOLC) ? 1 : 0;  // NaN -> false
            }
            __syncthreads();
            if (valid) {
                if (s_conv[quarter]) {
                    *(float4*)(g_vsol + eb) = make_float4(vn[0], vn[1], vn[2], vn[3]);
                    *(float4*)(g_vsol + eb + 4) = make_float4(vn[4], vn[5], vn[6], vn[7]);
                    __align__(16) __nv_bfloat16 hh[8], mm[8];
#pragma unroll
                    for (int j = 0; j < 8; ++j) split2(vn[j], hh[j], mm[j]);
                    *(uint4*)(g_Vh + eb) = *(uint4*)hh;
                    *(uint4*)(g_Vm + eb) = *(uint4*)mm;
                    if (t == 0) g_flag[row] = 1;
                } else {
                    *(float4*)(g_v + eb) = make_float4(vn[0], vn[1], vn[2], vn[3]);
                    *(float4*)(g_v + eb + 4) = make_float4(vn[4], vn[5], vn[6], vn[7]);
                    *(float4*)(g_u + eb) = make_float4(un[0], un[1], un[2], un[3]);
                    *(float4*)(g_u + eb + 4) = make_float4(un[4], un[5], un[6], un[7]);
                    __align__(16) __nv_bfloat16 hh[8], mm[8];
#pragma unroll
                    for (int j = 0; j < 8; ++j)
                        split2(ao[j] + vn[j] - un[j], hh[j], mm[j]);
                    *(uint4*)(g_Eh + eb) = *(uint4*)hh;
                    *(uint4*)(g_Em + eb) = *(uint4*)mm;
                }
            }
            __syncthreads();
        }
        gridbar();
    }
}

// ---- decode: CTAs 0-63 HMMA partials of vsol @ w; CTAs 64-127 copy enc ----
__global__ void __launch_bounds__(NTHR, 1) k_decode(float* __restrict__ enc,
                                                    const float* __restrict__ dec) {
    extern __shared__ char sm[];
    const uint32_t smb = smem_u32(sm);
    const int tid = threadIdx.x;
    const int lane = tid & 31, wrp = tid >> 5;
    int bid = blockIdx.x;

    if (bid >= 64) {
        if (enc) {
            const float4* src = (const float4*)g_vsol;
            float4* dst = (float4*)enc;
            for (int i = (bid - 64) * NTHR + tid; i < BATCH * MDIM / 4; i += 64 * NTHR)
                dst[i] = src[i];
        }
        return;
    }
    if (!dec) return;

    int ks = bid >> 5, unit = bid & 31;
    int tm = unit >> 2, tn = unit & 3;
    uint32_t dsw[2];
    int aoff[2], boff[2];
#pragma unroll
    for (int c = 0; c < 2; ++c) {
        int idx = tid + 512 * c;
        int rw = idx >> 3, q = idx & 7;
        dsw[c] = swz((uint32_t)(rw * 128 + q * 16));
        aoff[c] = (tm * 128 + rw) * MDIM + q * 8;
        boff[c] = (tn * 128 + rw) * MDIM + q * 8;
    }
    int wm = wrp >> 2, wn = wrp & 3;
    int rowa = wm * 32 + (lane & 7) + ((lane >> 3) & 1) * 8;
    int qa = lane >> 4;
    uint32_t offA[2];
#pragma unroll
    for (int mi = 0; mi < 2; ++mi)
        offA[mi] = swz((uint32_t)((rowa + mi * 16) * 128 + qa * 16));
    int rowb = wn * 32 + (lane & 7);
    int qb = (lane >> 3) & 1;
    uint32_t offB[4];
#pragma unroll
    for (int ni = 0; ni < 4; ++ni)
        offB[ni] = swz((uint32_t)((rowb + ni * 8) * 128 + qb * 16));

    float acc[2][4][4];
#pragma unroll
    for (int mi = 0; mi < 2; ++mi)
#pragma unroll
        for (int ni = 0; ni < 4; ++ni)
#pragma unroll
            for (int q = 0; q < 4; ++q) acc[mi][ni][q] = 0.f;

    hmma_tile(smb, ks * NSTAGE, g_Vh, g_Vh, g_Vm, g_Wh, g_Wm, g_Wh,
              aoff, boff, dsw, offA, offB, acc);

    float* dst = ks ? g_xkB : g_xkA;
    int cbase = tn * 128 + wn * 32 + 2 * (lane & 3);
#pragma unroll
    for (int mi = 0; mi < 2; ++mi)
#pragma unroll
        for (int half = 0; half < 2; ++half) {
            int ridx = wm * 32 + mi * 16 + (lane >> 2) + half * 8;
            int row = tm * 128 + ridx;
            float* p = dst + row * NDIM + cbase;
#pragma unroll
            for (int ni = 0; ni < 4; ++ni) {
                float2 v2 = make_float2(acc[mi][ni][half * 2], acc[mi][ni][half * 2 + 1]);
                *(float2*)(p + ni * 8) = v2;
            }
        }
}

__global__ void k_sum(float* __restrict__ dec) {
    int tid = blockIdx.x * blockDim.x + threadIdx.x, nt = gridDim.x * blockDim.x;
    const float4* pa = (const float4*)g_xkA;
    const float4* pb = (const float4*)g_xkB;
    float4* po = (float4*)dec;
    for (int i = tid; i < BATCH * NDIM / 4; i += nt) {
        float4 a = pa[i], b = pb[i];
        po[i] = make_float4(a.x + b.x, a.y + b.y, a.z + b.z, a.w + b.w);
    }
}

extern "C" void kernel_launch(void* const* d_in, const int* in_sizes, int n_in,
                              void* d_out, int out_size) {
    const float* x = nullptr;
    const float* w = nullptr;
    const float* Minv = nullptr;
    int small[2] = {0, 1}, si = 0;
    for (int i = 0; i < n_in; ++i) {
        if (in_sizes[i] == MDIM * MDIM && !Minv) Minv = (const float*)d_in[i];
        else if (si < 2) small[si++] = i;
    }
    x = (const float*)d_in[small[0]];
    w = (const float*)d_in[small[1]];

    float* out = (float*)d_out;
    float* enc = nullptr;
    float* dec = nullptr;
    if (out_size >= BATCH * MDIM + BATCH * NDIM) { enc = out; dec = out + (size_t)BATCH * MDIM; }
    else if (out_size == BATCH * NDIM) dec = out;
    else enc = out;

    cudaFuncSetAttribute(k_admm, cudaFuncAttributeMaxDynamicSharedMemorySize, SMEM_TOTAL);
    cudaFuncSetAttribute(k_decode, cudaFuncAttributeMaxDynamicSharedMemorySize, SMEM_TOTAL);
    k_init<<<128, 256>>>();
    k_prep<<<dim3(32, 32), dim3(32, 8)>>>(Minv);
    k_prepw<<<dim3(16, 32), dim3(32, 8)>>>(w);
    k_admm<<<GRID, NTHR, SMEM_TOTAL>>>(x, w);
    k_decode<<<GRID, NTHR, SMEM_TOTAL>>>(enc, dec);
    if (dec) k_sum<<<64, 256>>>(dec);
}